// round 7
// baseline (speedup 1.0000x reference)
#include <cuda_runtime.h>
#include <cuda_bf16.h>
#include <cstdint>
#include <math.h>

// ---------------------------------------------------------------------------
// GAT 4-layer network.
//   - CSR build (dst-sorted) once per call
//   - Layers 1-3: split-bf16 HMMA GEMM (mma.sync m16n8k16), 3-stage cp.async
//     pipeline, fused attention-coefficient epilogue.
//   - Layer 4: exact fp32 SIMT GEMM (tiny) + separate attcoef.
//   - FUSED per-node softmax + aggregation (k_attn_agg<H>): block per node,
//     smem edge weights, online-softmax chunking, register accumulators.
//   - BN+ELU fused with bf16 hi/lo re-split (dead stores elided per layer),
//     log_softmax.
// ---------------------------------------------------------------------------

#define MAXN 20000
#define MAXE 360000
#define MAXF 512
#define MAXH 8
#define SCAN_B 512

__device__ float g_h[MAXN * MAXF];
__device__ float g_y[MAXN * MAXF];
__device__ float g_agg[MAXN * MAXF];
__device__ float g_as[MAXN * MAXH];
__device__ float g_ad[MAXN * MAXH];
__device__ int   g_deg[MAXN];
__device__ int   g_rowptr[MAXN + 1];
__device__ int   g_cursor[MAXN];
__device__ int   g_srcs[MAXE];
__device__ float g_colsum[MAXF];
__device__ float g_colsq[MAXF];
__device__ int   g_bsums[64];
__device__ __nv_bfloat16 g_ahi[MAXN * MAXF];
__device__ __nv_bfloat16 g_alo[MAXN * MAXF];
__device__ __nv_bfloat16 g_bhi[MAXF * MAXF];
__device__ __nv_bfloat16 g_blo[MAXF * MAXF];

// ---------------------------------------------------------------------------
// PTX helpers
// ---------------------------------------------------------------------------
__device__ __forceinline__ uint32_t smem_to_u32(const void* p) {
    uint32_t a;
    asm("{ .reg .u64 t; cvta.to.shared.u64 t, %1; cvt.u32.u64 %0, t; }" : "=r"(a) : "l"(p));
    return a;
}
__device__ __forceinline__ void cp16(uint32_t s, const void* g) {
    asm volatile("cp.async.cg.shared.global [%0], [%1], 16;" :: "r"(s), "l"(g));
}
__device__ __forceinline__ void ldsm_x4(uint32_t* r, uint32_t addr) {
    asm volatile("ldmatrix.sync.aligned.m8n8.x4.shared.b16 {%0,%1,%2,%3}, [%4];"
        : "=r"(r[0]), "=r"(r[1]), "=r"(r[2]), "=r"(r[3]) : "r"(addr));
}
__device__ __forceinline__ void ldsm_x4_t(uint32_t* r, uint32_t addr) {
    asm volatile("ldmatrix.sync.aligned.m8n8.x4.trans.shared.b16 {%0,%1,%2,%3}, [%4];"
        : "=r"(r[0]), "=r"(r[1]), "=r"(r[2]), "=r"(r[3]) : "r"(addr));
}
__device__ __forceinline__ void mma16816(float* c, const uint32_t* a, const uint32_t* b) {
    asm volatile("mma.sync.aligned.m16n8k16.row.col.f32.bf16.bf16.f32 "
        "{%0,%1,%2,%3}, {%4,%5,%6,%7}, {%8,%9}, {%0,%1,%2,%3};"
        : "+f"(c[0]), "+f"(c[1]), "+f"(c[2]), "+f"(c[3])
        : "r"(a[0]), "r"(a[1]), "r"(a[2]), "r"(a[3]), "r"(b[0]), "r"(b[1]));
}

// ---------------------------------------------------------------------------
// CSR build
// ---------------------------------------------------------------------------
__global__ void k_zero_int(int* p, int n) {
    int i = blockIdx.x * blockDim.x + threadIdx.x;
    if (i < n) p[i] = 0;
}

__global__ void k_hist(const int* __restrict__ ei, int E, int N, int* __restrict__ deg) {
    int e = blockIdx.x * blockDim.x + threadIdx.x;
    if (e >= E + N) return;
    int dst = (e < E) ? ei[E + e] : (e - E);
    atomicAdd(&deg[dst], 1);
}

__global__ void k_scan1(const int* __restrict__ deg, int* __restrict__ rowptr,
                        int* __restrict__ bsums, int n) {
    __shared__ int sh[SCAN_B];
    int i = blockIdx.x * SCAN_B + threadIdx.x;
    int v = (i < n) ? deg[i] : 0;
    sh[threadIdx.x] = v;
    __syncthreads();
    for (int off = 1; off < SCAN_B; off <<= 1) {
        int t = 0;
        if ((int)threadIdx.x >= off) t = sh[threadIdx.x - off];
        __syncthreads();
        sh[threadIdx.x] += t;
        __syncthreads();
    }
    if (i < n) rowptr[i] = sh[threadIdx.x] - v;
    if (threadIdx.x == SCAN_B - 1) bsums[blockIdx.x] = sh[SCAN_B - 1];
}

__global__ void k_scan2(int* bsums, int nb) {
    if (threadIdx.x == 0) {
        int run = 0;
        for (int i = 0; i < nb; i++) { int v = bsums[i]; bsums[i] = run; run += v; }
    }
}

__global__ void k_scan3(int* __restrict__ rowptr, const int* __restrict__ bsums,
                        int n, int etot, int* __restrict__ cursor) {
    int i = blockIdx.x * blockDim.x + threadIdx.x;
    if (i < n) {
        int v = rowptr[i] + bsums[i / SCAN_B];
        rowptr[i] = v;
        cursor[i] = v;
    }
    if (i == 0) rowptr[n] = etot;
}

__global__ void k_scatter(const int* __restrict__ ei, int E, int N,
                          int* __restrict__ cursor, int* __restrict__ srcs) {
    int e = blockIdx.x * blockDim.x + threadIdx.x;
    if (e >= E + N) return;
    int src, dst;
    if (e < E) { src = ei[e]; dst = ei[E + e]; }
    else       { src = dst = e - E; }
    int p = atomicAdd(&cursor[dst], 1);
    srcs[p] = src;
}

// ---------------------------------------------------------------------------
// fp32 -> (bf16 hi, bf16 lo) split
// ---------------------------------------------------------------------------
__global__ void k_split(const float* __restrict__ x, __nv_bfloat16* __restrict__ hi,
                        __nv_bfloat16* __restrict__ lo, int n) {
    int i = (blockIdx.x * blockDim.x + threadIdx.x) * 4;
    if (i >= n) return;
    float4 v = *(const float4*)(x + i);
    __nv_bfloat16 h0 = __float2bfloat16(v.x), h1 = __float2bfloat16(v.y);
    __nv_bfloat16 h2 = __float2bfloat16(v.z), h3 = __float2bfloat16(v.w);
    __nv_bfloat16 l0 = __float2bfloat16(v.x - __bfloat162float(h0));
    __nv_bfloat16 l1 = __float2bfloat16(v.y - __bfloat162float(h1));
    __nv_bfloat16 l2 = __float2bfloat16(v.z - __bfloat162float(h2));
    __nv_bfloat16 l3 = __float2bfloat16(v.w - __bfloat162float(h3));
    __nv_bfloat162* ph = (__nv_bfloat162*)(hi + i);
    __nv_bfloat162* pl = (__nv_bfloat162*)(lo + i);
    ph[0] = __nv_bfloat162(h0, h1); ph[1] = __nv_bfloat162(h2, h3);
    pl[0] = __nv_bfloat162(l0, l1); pl[1] = __nv_bfloat162(l2, l3);
}

// ---------------------------------------------------------------------------
// split-bf16 HMMA GEMM + fused attention coefficients
// ---------------------------------------------------------------------------
#define STAGE_BYTES 37888
#define OFF_ALO 10240
#define OFF_BHI 20480
#define OFF_BLO 29184
#define MMA_SMEM (3 * STAGE_BYTES)

__global__ void __launch_bounds__(256, 2) k_mma_gemm(
    const __nv_bfloat16* __restrict__ Ahi, const __nv_bfloat16* __restrict__ Alo,
    const __nv_bfloat16* __restrict__ Bhi, const __nv_bfloat16* __restrict__ Blo,
    float* __restrict__ C, int M, int K, int Nn,
    const float* __restrict__ att_s, const float* __restrict__ att_d,
    float* __restrict__ out_s, float* __restrict__ out_d, int H) {
    extern __shared__ char smem[];
    uint32_t sbu = smem_to_u32(smem);
    int tid = threadIdx.x, lane = tid & 31, wid = tid >> 5;
    int wm = wid & 1, wn = wid >> 1;
    int row0 = blockIdx.y * 128, col0 = blockIdx.x * 128;

    float c[4][4][4];
#pragma unroll
    for (int i = 0; i < 4; i++)
#pragma unroll
        for (int j = 0; j < 4; j++) {
            c[i][j][0] = 0.f; c[i][j][1] = 0.f; c[i][j][2] = 0.f; c[i][j][3] = 0.f;
        }

    int nch = K >> 5;

    auto issue = [&](int ch) {
        uint32_t sb = sbu + (uint32_t)(ch % 3) * STAGE_BYTES;
        int k0 = ch << 5;
#pragma unroll
        for (int i = 0; i < 2; i++) {
            int g = tid + i * 256;
            int r = g >> 2, c8 = (g & 3) << 3;
            int row = row0 + r;
            if (row >= M) row = M - 1;
            size_t ga = (size_t)row * K + k0 + c8;
            uint32_t sa = sb + r * 80 + (c8 << 1);
            cp16(sa, Ahi + ga);
            cp16(sa + OFF_ALO, Alo + ga);
            int rb = g >> 4, cb = (g & 15) << 3;
            size_t gb = (size_t)(k0 + rb) * Nn + col0 + cb;
            uint32_t sB = sb + OFF_BHI + rb * 272 + (cb << 1);
            cp16(sB, Bhi + gb);
            cp16(sB + (OFF_BLO - OFF_BHI), Blo + gb);
        }
        asm volatile("cp.async.commit_group;" ::: "memory");
    };

    issue(0);
    issue(1);
    for (int ch = 0; ch < nch; ch++) {
        if (ch + 1 < nch)
            asm volatile("cp.async.wait_group 1;" ::: "memory");
        else
            asm volatile("cp.async.wait_group 0;" ::: "memory");
        __syncthreads();
        if (ch + 2 < nch) issue(ch + 2);

        uint32_t sb = sbu + (uint32_t)(ch % 3) * STAGE_BYTES;
#pragma unroll
        for (int kk2 = 0; kk2 < 2; kk2++) {
            int kk = kk2 << 4;
            uint32_t ah[4][4], al[4][4], bh[2][4], bl[2][4];
#pragma unroll
            for (int mt = 0; mt < 4; mt++) {
                uint32_t aoff = sb + (uint32_t)(wm * 64 + mt * 16 + (lane & 15)) * 80
                              + ((kk + ((lane >> 4) << 3)) << 1);
                ldsm_x4(ah[mt], aoff);
                ldsm_x4(al[mt], aoff + OFF_ALO);
            }
#pragma unroll
            for (int nt2 = 0; nt2 < 2; nt2++) {
                uint32_t boff = sb + OFF_BHI + (uint32_t)(kk + (lane & 15)) * 272
                              + ((wn * 32 + nt2 * 16 + ((lane >> 4) << 3)) << 1);
                ldsm_x4_t(bh[nt2], boff);
                ldsm_x4_t(bl[nt2], boff + (OFF_BLO - OFF_BHI));
            }
#pragma unroll
            for (int mt = 0; mt < 4; mt++)
#pragma unroll
                for (int nt = 0; nt < 4; nt++)
                    mma16816(c[mt][nt], ah[mt], &bh[nt >> 1][(nt & 1) << 1]);
#pragma unroll
            for (int mt = 0; mt < 4; mt++)
#pragma unroll
                for (int nt = 0; nt < 4; nt++)
                    mma16816(c[mt][nt], ah[mt], &bl[nt >> 1][(nt & 1) << 1]);
#pragma unroll
            for (int mt = 0; mt < 4; mt++)
#pragma unroll
                for (int nt = 0; nt < 4; nt++)
                    mma16816(c[mt][nt], al[mt], &bh[nt >> 1][(nt & 1) << 1]);
        }
    }

    // ---- C store ----
#pragma unroll
    for (int mt = 0; mt < 4; mt++) {
        int r = row0 + wm * 64 + mt * 16 + (lane >> 2);
#pragma unroll
        for (int nt = 0; nt < 4; nt++) {
            int col = col0 + wn * 32 + nt * 8 + ((lane & 3) << 1);
            if (r < M) {
                float2 v = make_float2(c[mt][nt][0], c[mt][nt][1]);
                *(float2*)(C + (size_t)r * Nn + col) = v;
            }
            if (r + 8 < M) {
                float2 v = make_float2(c[mt][nt][2], c[mt][nt][3]);
                *(float2*)(C + (size_t)(r + 8) * Nn + col) = v;
            }
        }
    }

    // ---- fused attention coefficients ----
    __syncthreads();
    float* sred = (float*)smem;          // [2][128]
    float* dred = sred + 256;            // [2][128]
    sred[tid] = 0.f;
    dred[tid] = 0.f;
    __syncthreads();

    float asv[4][2], adv[4][2];
#pragma unroll
    for (int nt = 0; nt < 4; nt++) {
        int col = col0 + wn * 32 + nt * 8 + ((lane & 3) << 1);
        asv[nt][0] = att_s[col];     asv[nt][1] = att_s[col + 1];
        adv[nt][0] = att_d[col];     adv[nt][1] = att_d[col + 1];
    }
#pragma unroll
    for (int mt = 0; mt < 4; mt++) {
        float s0 = 0.f, s1 = 0.f, d0 = 0.f, d1 = 0.f;
#pragma unroll
        for (int nt = 0; nt < 4; nt++) {
            s0 += c[mt][nt][0] * asv[nt][0] + c[mt][nt][1] * asv[nt][1];
            s1 += c[mt][nt][2] * asv[nt][0] + c[mt][nt][3] * asv[nt][1];
            d0 += c[mt][nt][0] * adv[nt][0] + c[mt][nt][1] * adv[nt][1];
            d1 += c[mt][nt][2] * adv[nt][0] + c[mt][nt][3] * adv[nt][1];
        }
#pragma unroll
        for (int o = 1; o <= 2; o <<= 1) {
            s0 += __shfl_xor_sync(0xffffffffu, s0, o);
            s1 += __shfl_xor_sync(0xffffffffu, s1, o);
            d0 += __shfl_xor_sync(0xffffffffu, d0, o);
            d1 += __shfl_xor_sync(0xffffffffu, d1, o);
        }
        if ((lane & 3) == 0) {
            int hh = wn >> 1;
            int rloc = wm * 64 + mt * 16 + (lane >> 2);
            atomicAdd(&sred[hh * 128 + rloc], s0);
            atomicAdd(&sred[hh * 128 + rloc + 8], s1);
            atomicAdd(&dred[hh * 128 + rloc], d0);
            atomicAdd(&dred[hh * 128 + rloc + 8], d1);
        }
    }
    __syncthreads();
    {
        int hh = tid >> 7;
        int rloc = tid & 127;
        int row = row0 + rloc;
        if (row < M) {
            int hglob = (col0 >> 6) + hh;
            out_s[row * H + hglob] = sred[hh * 128 + rloc];
            out_d[row * H + hglob] = dred[hh * 128 + rloc];
        }
    }
}

// ---------------------------------------------------------------------------
// fp32 SIMT SGEMM (layer 4 only)
// ---------------------------------------------------------------------------
__global__ void k_sgemm(const float* __restrict__ A, const float* __restrict__ B,
                        float* __restrict__ C, int M, int K, int Nn) {
    __shared__ float As[16][68];
    __shared__ float Bs[16][68];
    int tid = threadIdx.x;
    int tx = tid & 15;
    int ty = tid >> 4;
    int row0 = blockIdx.y * 64;
    int col0 = blockIdx.x * 64;

    int arow = tid >> 2;
    int acol = (tid & 3) * 4;
    int brow = tid >> 4;
    int bcol = (tid & 15) * 4;

    float acc[4][4];
#pragma unroll
    for (int i = 0; i < 4; i++)
#pragma unroll
        for (int j = 0; j < 4; j++) acc[i][j] = 0.f;

    for (int k0 = 0; k0 < K; k0 += 16) {
        float4 av = make_float4(0.f, 0.f, 0.f, 0.f);
        if (row0 + arow < M)
            av = *(const float4*)(A + (size_t)(row0 + arow) * K + k0 + acol);
        As[acol + 0][arow] = av.x;
        As[acol + 1][arow] = av.y;
        As[acol + 2][arow] = av.z;
        As[acol + 3][arow] = av.w;

        float4 bv = make_float4(0.f, 0.f, 0.f, 0.f);
        if (col0 + bcol < Nn)
            bv = *(const float4*)(B + (size_t)(k0 + brow) * Nn + col0 + bcol);
        Bs[brow][bcol + 0] = bv.x;
        Bs[brow][bcol + 1] = bv.y;
        Bs[brow][bcol + 2] = bv.z;
        Bs[brow][bcol + 3] = bv.w;
        __syncthreads();

#pragma unroll
        for (int kk = 0; kk < 16; kk++) {
            float4 a4 = *(const float4*)&As[kk][ty * 4];
            float4 b4 = *(const float4*)&Bs[kk][tx * 4];
            float a[4] = {a4.x, a4.y, a4.z, a4.w};
            float b[4] = {b4.x, b4.y, b4.z, b4.w};
#pragma unroll
            for (int i = 0; i < 4; i++)
#pragma unroll
                for (int j = 0; j < 4; j++) acc[i][j] += a[i] * b[j];
        }
        __syncthreads();
    }

#pragma unroll
    for (int i = 0; i < 4; i++) {
        int r = row0 + ty * 4 + i;
        if (r >= M) break;
#pragma unroll
        for (int j = 0; j < 4; j++) {
            int cc = col0 + tx * 4 + j;
            if (cc < Nn) C[(size_t)r * Nn + cc] = acc[i][j];
        }
    }
}

// ---------------------------------------------------------------------------
// Attention coefficients (layer 4 only)
// ---------------------------------------------------------------------------
__global__ void k_attcoef(const float* __restrict__ h, const float* __restrict__ as,
                          const float* __restrict__ ad, float* __restrict__ out_s,
                          float* __restrict__ out_d, int N, int H, int C) {
    int wid = blockIdx.x * (blockDim.x >> 5) + (threadIdx.x >> 5);
    int lane = threadIdx.x & 31;
    if (wid >= N * H) return;
    int n = wid / H;
    int hh = wid - n * H;
    int F = H * C;
    const float* hr = h + (size_t)n * F + hh * C;
    const float* asr = as + hh * C;
    const float* adr = ad + hh * C;
    float s = 0.f, d = 0.f;
    for (int c = lane; c < C; c += 32) {
        float v = hr[c];
        s += v * asr[c];
        d += v * adr[c];
    }
#pragma unroll
    for (int o = 16; o; o >>= 1) {
        s += __shfl_xor_sync(0xffffffffu, s, o);
        d += __shfl_xor_sync(0xffffffffu, d, o);
    }
    if (lane == 0) {
        out_s[wid] = s;
        out_d[wid] = d;
    }
}

// ---------------------------------------------------------------------------
// FUSED per-node segment softmax + aggregation.
// Block (128 thr) per node. Online softmax over chunks of CAP edges.
// Phase 1: gather a_s rows (vectorized), leaky-relu, chunk max/sum reductions,
//          exp weights into smem. Phase 2: feature threads aggregate.
// ---------------------------------------------------------------------------
#define AA_CAP 512

template <int H>
__global__ void __launch_bounds__(128) k_attn_agg(
    const float* __restrict__ h, const float* __restrict__ a_s,
    const float* __restrict__ a_d, const int* __restrict__ rowptr,
    const int* __restrict__ srcs, const float* __restrict__ bias,
    float* __restrict__ out, int F, int C) {
    __shared__ float sw[AA_CAP * H];
    __shared__ int   ssrc[AA_CAP];
    __shared__ float red[H][4];
    __shared__ float cmx[H], bm[H], bs[H], bfo[H], bfc[H];

    int n = blockIdx.x;
    int tid = threadIdx.x, lane = tid & 31, wrp = tid >> 5;
    int st = rowptr[n], en = rowptr[n + 1];

    float adv[H];
#pragma unroll
    for (int hh = 0; hh < H; hh++) adv[hh] = a_d[n * H + hh];

    if (tid < H) { bm[tid] = -1e30f; bs[tid] = 0.f; }

    int f4 = tid << 2;
    bool act = f4 < F;
    int myh = act ? f4 / C : 0;
    float4 acc = make_float4(0.f, 0.f, 0.f, 0.f);
    __syncthreads();

    for (int c0 = st; c0 < en; c0 += AA_CAP) {
        int cn = min(en - c0, AA_CAP);

        // phase 1a: gather + leaky-relu, thread-local per-head max
        float lmax[H];
#pragma unroll
        for (int hh = 0; hh < H; hh++) lmax[hh] = -1e30f;
        for (int i = tid; i < cn; i += 128) {
            int src = srcs[c0 + i];
            ssrc[i] = src;
            float av[H];
            if (H == 8) {
                float4 a = *(const float4*)(a_s + src * 8);
                float4 b = *(const float4*)(a_s + src * 8 + 4);
                av[0] = a.x; av[1] = a.y; av[2] = a.z; av[3] = a.w;
                av[4] = b.x; av[5] = b.y; av[6] = b.z; av[7] = b.w;
            } else if (H == 4) {
                float4 a = *(const float4*)(a_s + src * 4);
                av[0] = a.x; av[1] = a.y; av[2] = a.z; av[3] = a.w;
            } else if (H == 2) {
                float2 a = *(const float2*)(a_s + src * 2);
                av[0] = a.x; av[1] = a.y;
            } else {
                av[0] = a_s[src];
            }
#pragma unroll
            for (int hh = 0; hh < H; hh++) {
                float v = av[hh] + adv[hh];
                v = v >= 0.f ? v : 0.2f * v;
                sw[i * H + hh] = v;
                lmax[hh] = fmaxf(lmax[hh], v);
            }
        }
        // block-reduce per-head max
#pragma unroll
        for (int hh = 0; hh < H; hh++) {
            float v = lmax[hh];
#pragma unroll
            for (int o = 16; o; o >>= 1) v = fmaxf(v, __shfl_xor_sync(0xffffffffu, v, o));
            if (lane == 0) red[hh][wrp] = v;
        }
        __syncthreads();
        if (tid < H) {
            float v = fmaxf(fmaxf(red[tid][0], red[tid][1]), fmaxf(red[tid][2], red[tid][3]));
            cmx[tid] = v;
        }
        __syncthreads();

        // phase 1b: exp + thread-local per-head sum
        float lsum[H];
#pragma unroll
        for (int hh = 0; hh < H; hh++) lsum[hh] = 0.f;
        for (int i = tid; i < cn; i += 128) {
#pragma unroll
            for (int hh = 0; hh < H; hh++) {
                float ex = __expf(sw[i * H + hh] - cmx[hh]);
                sw[i * H + hh] = ex;
                lsum[hh] += ex;
            }
        }
#pragma unroll
        for (int hh = 0; hh < H; hh++) {
            float v = lsum[hh];
#pragma unroll
            for (int o = 16; o; o >>= 1) v += __shfl_xor_sync(0xffffffffu, v, o);
            if (lane == 0) red[hh][wrp] = v;
        }
        __syncthreads();
        if (tid < H) {
            float cs = red[tid][0] + red[tid][1] + red[tid][2] + red[tid][3];
            float om = bm[tid], cm = cmx[tid];
            float nm = fmaxf(om, cm);
            float fo = __expf(om - nm);
            float fc = __expf(cm - nm);
            bs[tid] = bs[tid] * fo + cs * fc;
            bm[tid] = nm;
            bfo[tid] = fo;
            bfc[tid] = fc;
        }
        __syncthreads();

        // phase 2: feature aggregation for this chunk
        if (act) {
            float fo = bfo[myh], fc = bfc[myh];
            float cx = 0.f, cy = 0.f, cz = 0.f, cw = 0.f;
            int i = 0;
            for (; i + 4 <= cn; i += 4) {
                int s0 = ssrc[i], s1 = ssrc[i + 1], s2 = ssrc[i + 2], s3 = ssrc[i + 3];
                float a0 = sw[(i + 0) * H + myh];
                float a1 = sw[(i + 1) * H + myh];
                float a2 = sw[(i + 2) * H + myh];
                float a3 = sw[(i + 3) * H + myh];
                float4 v0 = *(const float4*)(h + (size_t)s0 * F + f4);
                float4 v1 = *(const float4*)(h + (size_t)s1 * F + f4);
                float4 v2 = *(const float4*)(h + (size_t)s2 * F + f4);
                float4 v3 = *(const float4*)(h + (size_t)s3 * F + f4);
                cx += v0.x * a0 + v1.x * a1 + v2.x * a2 + v3.x * a3;
                cy += v0.y * a0 + v1.y * a1 + v2.y * a2 + v3.y * a3;
                cz += v0.z * a0 + v1.z * a1 + v2.z * a2 + v3.z * a3;
                cw += v0.w * a0 + v1.w * a1 + v2.w * a2 + v3.w * a3;
            }
            for (; i < cn; i++) {
                int s = ssrc[i];
                float a = sw[i * H + myh];
                float4 v = *(const float4*)(h + (size_t)s * F + f4);
                cx += v.x * a; cy += v.y * a; cz += v.z * a; cw += v.w * a;
            }
            acc.x = acc.x * fo + cx * fc;
            acc.y = acc.y * fo + cy * fc;
            acc.z = acc.z * fo + cz * fc;
            acc.w = acc.w * fo + cw * fc;
        }
        __syncthreads();  // protect sw/ssrc before next chunk
    }

    if (act) {
        float inv = 1.f / bs[myh];
        float4 b = *(const float4*)(bias + f4);
        float4 o;
        o.x = acc.x * inv + b.x;
        o.y = acc.y * inv + b.y;
        o.z = acc.z * inv + b.z;
        o.w = acc.w * inv + b.w;
        *(float4*)(out + (size_t)n * F + f4) = o;
    }
}

// ---------------------------------------------------------------------------
// BatchNorm + ELU (optional fp32 store, optional bf16 hi/lo split store)
// ---------------------------------------------------------------------------
__global__ void k_zero_f2(float* a, float* b, int n) {
    int i = blockIdx.x * blockDim.x + threadIdx.x;
    if (i < n) { a[i] = 0.f; b[i] = 0.f; }
}

__global__ void k_bnstats(const float* __restrict__ x, float* __restrict__ csum,
                          float* __restrict__ csq, int N, int F) {
    int c = threadIdx.x;
    float s = 0.f, sq = 0.f;
    for (int r = blockIdx.x; r < N; r += gridDim.x) {
        float v = x[(size_t)r * F + c];
        s += v;
        sq += v * v;
    }
    atomicAdd(&csum[c], s);
    atomicAdd(&csq[c], sq);
}

__global__ void k_bnapply_split(const float* __restrict__ in, float* __restrict__ out,
                                __nv_bfloat16* __restrict__ hi, __nv_bfloat16* __restrict__ lo,
                                const float* __restrict__ csum, const float* __restrict__ csq,
                                const float* __restrict__ gamma, const float* __restrict__ beta,
                                int N, int F, int store_f32, int store_bf16) {
    int idx = blockIdx.x * blockDim.x + threadIdx.x;
    if (idx >= N * F) return;
    int c = idx % F;
    float invN = 1.f / (float)N;
    float mean = csum[c] * invN;
    float var = csq[c] * invN - mean * mean;
    float v = (in[idx] - mean) * rsqrtf(var + 1e-5f) * gamma[c] + beta[c];
    v = v > 0.f ? v : (__expf(v) - 1.f);
    if (store_f32) out[idx] = v;
    if (store_bf16) {
        __nv_bfloat16 h = __float2bfloat16(v);
        hi[idx] = h;
        lo[idx] = __float2bfloat16(v - __bfloat162float(h));
    }
}

// ---------------------------------------------------------------------------
// log_softmax over 16 classes
// ---------------------------------------------------------------------------
__global__ void k_logsoftmax16(const float* __restrict__ in, float* __restrict__ out, int N) {
    int n = blockIdx.x * blockDim.x + threadIdx.x;
    if (n >= N) return;
    const float* r = in + n * 16;
    float mx = r[0];
#pragma unroll
    for (int j = 1; j < 16; j++) mx = fmaxf(mx, r[j]);
    float s = 0.f;
#pragma unroll
    for (int j = 0; j < 16; j++) s += __expf(r[j] - mx);
    float ls = logf(s) + mx;
    float* o = out + n * 16;
#pragma unroll
    for (int j = 0; j < 16; j++) o[j] = r[j] - ls;
}

// ---------------------------------------------------------------------------
// Host orchestration
// ---------------------------------------------------------------------------
extern "C" void kernel_launch(void* const* d_in, const int* in_sizes, int n_in,
                              void* d_out, int out_size) {
    const float* x = (const float*)d_in[0];
    const int* ei = (const int*)d_in[1];
    int N = in_sizes[0] / 512;
    int E = in_sizes[1] / 2;
    int Etot = E + N;

    float *p_h, *p_y, *p_agg, *p_as, *p_ad, *p_csum, *p_csq;
    int *p_deg, *p_rowptr, *p_cursor, *p_srcs, *p_bsums;
    __nv_bfloat16 *p_ahi, *p_alo, *p_bhi, *p_blo;
    cudaGetSymbolAddress((void**)&p_h, g_h);
    cudaGetSymbolAddress((void**)&p_y, g_y);
    cudaGetSymbolAddress((void**)&p_agg, g_agg);
    cudaGetSymbolAddress((void**)&p_as, g_as);
    cudaGetSymbolAddress((void**)&p_ad, g_ad);
    cudaGetSymbolAddress((void**)&p_csum, g_colsum);
    cudaGetSymbolAddress((void**)&p_csq, g_colsq);
    cudaGetSymbolAddress((void**)&p_deg, g_deg);
    cudaGetSymbolAddress((void**)&p_rowptr, g_rowptr);
    cudaGetSymbolAddress((void**)&p_cursor, g_cursor);
    cudaGetSymbolAddress((void**)&p_srcs, g_srcs);
    cudaGetSymbolAddress((void**)&p_bsums, g_bsums);
    cudaGetSymbolAddress((void**)&p_ahi, g_ahi);
    cudaGetSymbolAddress((void**)&p_alo, g_alo);
    cudaGetSymbolAddress((void**)&p_bhi, g_bhi);
    cudaGetSymbolAddress((void**)&p_blo, g_blo);

    cudaFuncSetAttribute(k_mma_gemm, cudaFuncAttributeMaxDynamicSharedMemorySize, MMA_SMEM);

    struct Cfg { int Fin, H, C, iW; bool bn; };
    const Cfg cfgs[4] = {
        {512, 8, 64, 2, true},
        {512, 4, 64, 8, true},
        {256, 2, 64, 14, true},
        {128, 1, 16, 20, false},
    };

    // ---- Layer-1 prep + GEMM ----
    {
        int nel = N * 512;
        k_zero_int<<<(N + 255) / 256, 256>>>(p_deg, N);
        k_split<<<(nel / 4 + 255) / 256, 256>>>(x, p_ahi, p_alo, nel);
        int nw = 512 * 512;
        k_split<<<(nw / 4 + 255) / 256, 256>>>((const float*)d_in[2], p_bhi, p_blo, nw);
        dim3 gg(512 / 128, (N + 127) / 128);
        k_mma_gemm<<<gg, 256, MMA_SMEM>>>(p_ahi, p_alo, p_bhi, p_blo, p_h, N, 512, 512,
                                          (const float*)d_in[3], (const float*)d_in[4],
                                          p_as, p_ad, 8);
    }

    // ---- CSR build ----
    k_hist<<<(Etot + 255) / 256, 256>>>(ei, E, N, p_deg);
    int nblk = (N + SCAN_B - 1) / SCAN_B;
    k_scan1<<<nblk, SCAN_B>>>(p_deg, p_rowptr, p_bsums, N);
    k_scan2<<<1, 32>>>(p_bsums, nblk);
    k_scan3<<<(N + 255) / 256, 256>>>(p_rowptr, p_bsums, N, Etot, p_cursor);
    k_scatter<<<(Etot + 255) / 256, 256>>>(ei, E, N, p_cursor, p_srcs);

    const float* in = x;
    for (int li = 0; li < 4; li++) {
        const Cfg& cf = cfgs[li];
        int F = cf.H * cf.C;
        const float* W  = (const float*)d_in[cf.iW + 0];
        const float* as = (const float*)d_in[cf.iW + 1];
        const float* ad = (const float*)d_in[cf.iW + 2];
        const float* bi = (const float*)d_in[cf.iW + 3];

        if (li >= 1 && li < 3) {
            int nw = cf.Fin * F;
            k_split<<<(nw / 4 + 255) / 256, 256>>>(W, p_bhi, p_blo, nw);
            dim3 gg(F / 128, (N + 127) / 128);
            k_mma_gemm<<<gg, 256, MMA_SMEM>>>(p_ahi, p_alo, p_bhi, p_blo, p_h, N, cf.Fin, F,
                                              as, ad, p_as, p_ad, cf.H);
        } else if (li == 3) {
            dim3 ggrid((F + 63) / 64, (N + 63) / 64);
            k_sgemm<<<ggrid, 256>>>(in, W, p_h, N, cf.Fin, F);
            int pairs = N * cf.H;
            k_attcoef<<<(pairs + 3) / 4, 128>>>(p_h, as, ad, p_as, p_ad, N, cf.H, cf.C);
        }

        // fused softmax + aggregation
        switch (cf.H) {
            case 8: k_attn_agg<8><<<N, 128>>>(p_h, p_as, p_ad, p_rowptr, p_srcs, bi, p_agg, F, cf.C); break;
            case 4: k_attn_agg<4><<<N, 128>>>(p_h, p_as, p_ad, p_rowptr, p_srcs, bi, p_agg, F, cf.C); break;
            case 2: k_attn_agg<2><<<N, 128>>>(p_h, p_as, p_ad, p_rowptr, p_srcs, bi, p_agg, F, cf.C); break;
            default: k_attn_agg<1><<<N, 128>>>(p_h, p_as, p_ad, p_rowptr, p_srcs, bi, p_agg, F, cf.C); break;
        }

        if (cf.bn) {
            const float* gamma = (const float*)d_in[cf.iW + 4];
            const float* beta  = (const float*)d_in[cf.iW + 5];
            k_zero_f2<<<1, F>>>(p_csum, p_csq, F);
            k_bnstats<<<240, F>>>(p_agg, p_csum, p_csq, N, F);
            int store_f32 = (li == 2) ? 1 : 0;   // only layer-3 output read as fp32 (by L4 sgemm)
            int store_bf16 = (li < 2) ? 1 : 0;   // only layers 1-2 feed MMA GEMMs
            k_bnapply_split<<<(N * F + 255) / 256, 256>>>(p_agg, p_y, p_ahi, p_alo,
                                                          p_csum, p_csq, gamma, beta, N, F,
                                                          store_f32, store_bf16);
            in = p_y;
        } else {
            k_logsoftmax16<<<(N + 255) / 256, 256>>>(p_agg, (float*)d_out, N);
        }
    }
}

// round 8
// speedup vs baseline: 1.1048x; 1.1048x over previous
#include <cuda_runtime.h>
#include <cuda_bf16.h>
#include <cstdint>
#include <math.h>

// ---------------------------------------------------------------------------
// GAT 4-layer network. (R6 structure + warp-per-node k_attn + dead-store BN)
//   - CSR build (dst-sorted) once per call
//   - Layers 1-3: split-bf16 HMMA GEMM (mma.sync m16n8k16), 3-stage cp.async
//     pipeline, fused attention-coefficient epilogue.
//   - Layer 4: exact fp32 SIMT GEMM (tiny) + separate attcoef.
//   - k_attn: warp per node, all heads per lane (vectorized a_s row gather),
//     head-major edge weights; k_agg: block per node, float4 + unroll-8.
//   - BN+ELU with per-layer dead-store elision; log_softmax.
// ---------------------------------------------------------------------------

#define MAXN 20000
#define MAXE 360000
#define MAXF 512
#define MAXH 8
#define SCAN_B 512

__device__ float g_h[MAXN * MAXF];
__device__ float g_y[MAXN * MAXF];
__device__ float g_agg[MAXN * MAXF];
__device__ float g_as[MAXN * MAXH];
__device__ float g_ad[MAXN * MAXH];
__device__ float g_w[MAXE * MAXH];     // head-major: [H][Etot]
__device__ float g_invs[MAXN * MAXH];
__device__ int   g_deg[MAXN];
__device__ int   g_rowptr[MAXN + 1];
__device__ int   g_cursor[MAXN];
__device__ int   g_srcs[MAXE];
__device__ float g_colsum[MAXF];
__device__ float g_colsq[MAXF];
__device__ int   g_bsums[64];
__device__ __nv_bfloat16 g_ahi[MAXN * MAXF];
__device__ __nv_bfloat16 g_alo[MAXN * MAXF];
__device__ __nv_bfloat16 g_bhi[MAXF * MAXF];
__device__ __nv_bfloat16 g_blo[MAXF * MAXF];

// ---------------------------------------------------------------------------
// PTX helpers
// ---------------------------------------------------------------------------
__device__ __forceinline__ uint32_t smem_to_u32(const void* p) {
    uint32_t a;
    asm("{ .reg .u64 t; cvta.to.shared.u64 t, %1; cvt.u32.u64 %0, t; }" : "=r"(a) : "l"(p));
    return a;
}
__device__ __forceinline__ void cp16(uint32_t s, const void* g) {
    asm volatile("cp.async.cg.shared.global [%0], [%1], 16;" :: "r"(s), "l"(g));
}
__device__ __forceinline__ void ldsm_x4(uint32_t* r, uint32_t addr) {
    asm volatile("ldmatrix.sync.aligned.m8n8.x4.shared.b16 {%0,%1,%2,%3}, [%4];"
        : "=r"(r[0]), "=r"(r[1]), "=r"(r[2]), "=r"(r[3]) : "r"(addr));
}
__device__ __forceinline__ void ldsm_x4_t(uint32_t* r, uint32_t addr) {
    asm volatile("ldmatrix.sync.aligned.m8n8.x4.trans.shared.b16 {%0,%1,%2,%3}, [%4];"
        : "=r"(r[0]), "=r"(r[1]), "=r"(r[2]), "=r"(r[3]) : "r"(addr));
}
__device__ __forceinline__ void mma16816(float* c, const uint32_t* a, const uint32_t* b) {
    asm volatile("mma.sync.aligned.m16n8k16.row.col.f32.bf16.bf16.f32 "
        "{%0,%1,%2,%3}, {%4,%5,%6,%7}, {%8,%9}, {%0,%1,%2,%3};"
        : "+f"(c[0]), "+f"(c[1]), "+f"(c[2]), "+f"(c[3])
        : "r"(a[0]), "r"(a[1]), "r"(a[2]), "r"(a[3]), "r"(b[0]), "r"(b[1]));
}

// ---------------------------------------------------------------------------
// CSR build
// ---------------------------------------------------------------------------
__global__ void k_zero_int(int* p, int n) {
    int i = blockIdx.x * blockDim.x + threadIdx.x;
    if (i < n) p[i] = 0;
}

__global__ void k_hist(const int* __restrict__ ei, int E, int N, int* __restrict__ deg) {
    int e = blockIdx.x * blockDim.x + threadIdx.x;
    if (e >= E + N) return;
    int dst = (e < E) ? ei[E + e] : (e - E);
    atomicAdd(&deg[dst], 1);
}

__global__ void k_scan1(const int* __restrict__ deg, int* __restrict__ rowptr,
                        int* __restrict__ bsums, int n) {
    __shared__ int sh[SCAN_B];
    int i = blockIdx.x * SCAN_B + threadIdx.x;
    int v = (i < n) ? deg[i] : 0;
    sh[threadIdx.x] = v;
    __syncthreads();
    for (int off = 1; off < SCAN_B; off <<= 1) {
        int t = 0;
        if ((int)threadIdx.x >= off) t = sh[threadIdx.x - off];
        __syncthreads();
        sh[threadIdx.x] += t;
        __syncthreads();
    }
    if (i < n) rowptr[i] = sh[threadIdx.x] - v;
    if (threadIdx.x == SCAN_B - 1) bsums[blockIdx.x] = sh[SCAN_B - 1];
}

__global__ void k_scan2(int* bsums, int nb) {
    if (threadIdx.x == 0) {
        int run = 0;
        for (int i = 0; i < nb; i++) { int v = bsums[i]; bsums[i] = run; run += v; }
    }
}

__global__ void k_scan3(int* __restrict__ rowptr, const int* __restrict__ bsums,
                        int n, int etot, int* __restrict__ cursor) {
    int i = blockIdx.x * blockDim.x + threadIdx.x;
    if (i < n) {
        int v = rowptr[i] + bsums[i / SCAN_B];
        rowptr[i] = v;
        cursor[i] = v;
    }
    if (i == 0) rowptr[n] = etot;
}

__global__ void k_scatter(const int* __restrict__ ei, int E, int N,
                          int* __restrict__ cursor, int* __restrict__ srcs) {
    int e = blockIdx.x * blockDim.x + threadIdx.x;
    if (e >= E + N) return;
    int src, dst;
    if (e < E) { src = ei[e]; dst = ei[E + e]; }
    else       { src = dst = e - E; }
    int p = atomicAdd(&cursor[dst], 1);
    srcs[p] = src;
}

// ---------------------------------------------------------------------------
// fp32 -> (bf16 hi, bf16 lo) split
// ---------------------------------------------------------------------------
__global__ void k_split(const float* __restrict__ x, __nv_bfloat16* __restrict__ hi,
                        __nv_bfloat16* __restrict__ lo, int n) {
    int i = (blockIdx.x * blockDim.x + threadIdx.x) * 4;
    if (i >= n) return;
    float4 v = *(const float4*)(x + i);
    __nv_bfloat16 h0 = __float2bfloat16(v.x), h1 = __float2bfloat16(v.y);
    __nv_bfloat16 h2 = __float2bfloat16(v.z), h3 = __float2bfloat16(v.w);
    __nv_bfloat16 l0 = __float2bfloat16(v.x - __bfloat162float(h0));
    __nv_bfloat16 l1 = __float2bfloat16(v.y - __bfloat162float(h1));
    __nv_bfloat16 l2 = __float2bfloat16(v.z - __bfloat162float(h2));
    __nv_bfloat16 l3 = __float2bfloat16(v.w - __bfloat162float(h3));
    __nv_bfloat162* ph = (__nv_bfloat162*)(hi + i);
    __nv_bfloat162* pl = (__nv_bfloat162*)(lo + i);
    ph[0] = __nv_bfloat162(h0, h1); ph[1] = __nv_bfloat162(h2, h3);
    pl[0] = __nv_bfloat162(l0, l1); pl[1] = __nv_bfloat162(l2, l3);
}

// ---------------------------------------------------------------------------
// split-bf16 HMMA GEMM + fused attention coefficients
// ---------------------------------------------------------------------------
#define STAGE_BYTES 37888
#define OFF_ALO 10240
#define OFF_BHI 20480
#define OFF_BLO 29184
#define MMA_SMEM (3 * STAGE_BYTES)

__global__ void __launch_bounds__(256, 2) k_mma_gemm(
    const __nv_bfloat16* __restrict__ Ahi, const __nv_bfloat16* __restrict__ Alo,
    const __nv_bfloat16* __restrict__ Bhi, const __nv_bfloat16* __restrict__ Blo,
    float* __restrict__ C, int M, int K, int Nn,
    const float* __restrict__ att_s, const float* __restrict__ att_d,
    float* __restrict__ out_s, float* __restrict__ out_d, int H) {
    extern __shared__ char smem[];
    uint32_t sbu = smem_to_u32(smem);
    int tid = threadIdx.x, lane = tid & 31, wid = tid >> 5;
    int wm = wid & 1, wn = wid >> 1;
    int row0 = blockIdx.y * 128, col0 = blockIdx.x * 128;

    float c[4][4][4];
#pragma unroll
    for (int i = 0; i < 4; i++)
#pragma unroll
        for (int j = 0; j < 4; j++) {
            c[i][j][0] = 0.f; c[i][j][1] = 0.f; c[i][j][2] = 0.f; c[i][j][3] = 0.f;
        }

    int nch = K >> 5;

    auto issue = [&](int ch) {
        uint32_t sb = sbu + (uint32_t)(ch % 3) * STAGE_BYTES;
        int k0 = ch << 5;
#pragma unroll
        for (int i = 0; i < 2; i++) {
            int g = tid + i * 256;
            int r = g >> 2, c8 = (g & 3) << 3;
            int row = row0 + r;
            if (row >= M) row = M - 1;
            size_t ga = (size_t)row * K + k0 + c8;
            uint32_t sa = sb + r * 80 + (c8 << 1);
            cp16(sa, Ahi + ga);
            cp16(sa + OFF_ALO, Alo + ga);
            int rb = g >> 4, cb = (g & 15) << 3;
            size_t gb = (size_t)(k0 + rb) * Nn + col0 + cb;
            uint32_t sB = sb + OFF_BHI + rb * 272 + (cb << 1);
            cp16(sB, Bhi + gb);
            cp16(sB + (OFF_BLO - OFF_BHI), Blo + gb);
        }
        asm volatile("cp.async.commit_group;" ::: "memory");
    };

    issue(0);
    issue(1);
    for (int ch = 0; ch < nch; ch++) {
        if (ch + 1 < nch)
            asm volatile("cp.async.wait_group 1;" ::: "memory");
        else
            asm volatile("cp.async.wait_group 0;" ::: "memory");
        __syncthreads();
        if (ch + 2 < nch) issue(ch + 2);

        uint32_t sb = sbu + (uint32_t)(ch % 3) * STAGE_BYTES;
#pragma unroll
        for (int kk2 = 0; kk2 < 2; kk2++) {
            int kk = kk2 << 4;
            uint32_t ah[4][4], al[4][4], bh[2][4], bl[2][4];
#pragma unroll
            for (int mt = 0; mt < 4; mt++) {
                uint32_t aoff = sb + (uint32_t)(wm * 64 + mt * 16 + (lane & 15)) * 80
                              + ((kk + ((lane >> 4) << 3)) << 1);
                ldsm_x4(ah[mt], aoff);
                ldsm_x4(al[mt], aoff + OFF_ALO);
            }
#pragma unroll
            for (int nt2 = 0; nt2 < 2; nt2++) {
                uint32_t boff = sb + OFF_BHI + (uint32_t)(kk + (lane & 15)) * 272
                              + ((wn * 32 + nt2 * 16 + ((lane >> 4) << 3)) << 1);
                ldsm_x4_t(bh[nt2], boff);
                ldsm_x4_t(bl[nt2], boff + (OFF_BLO - OFF_BHI));
            }
#pragma unroll
            for (int mt = 0; mt < 4; mt++)
#pragma unroll
                for (int nt = 0; nt < 4; nt++)
                    mma16816(c[mt][nt], ah[mt], &bh[nt >> 1][(nt & 1) << 1]);
#pragma unroll
            for (int mt = 0; mt < 4; mt++)
#pragma unroll
                for (int nt = 0; nt < 4; nt++)
                    mma16816(c[mt][nt], ah[mt], &bl[nt >> 1][(nt & 1) << 1]);
#pragma unroll
            for (int mt = 0; mt < 4; mt++)
#pragma unroll
                for (int nt = 0; nt < 4; nt++)
                    mma16816(c[mt][nt], al[mt], &bh[nt >> 1][(nt & 1) << 1]);
        }
    }

    // ---- C store ----
#pragma unroll
    for (int mt = 0; mt < 4; mt++) {
        int r = row0 + wm * 64 + mt * 16 + (lane >> 2);
#pragma unroll
        for (int nt = 0; nt < 4; nt++) {
            int col = col0 + wn * 32 + nt * 8 + ((lane & 3) << 1);
            if (r < M) {
                float2 v = make_float2(c[mt][nt][0], c[mt][nt][1]);
                *(float2*)(C + (size_t)r * Nn + col) = v;
            }
            if (r + 8 < M) {
                float2 v = make_float2(c[mt][nt][2], c[mt][nt][3]);
                *(float2*)(C + (size_t)(r + 8) * Nn + col) = v;
            }
        }
    }

    // ---- fused attention coefficients ----
    __syncthreads();
    float* sred = (float*)smem;          // [2][128]
    float* dred = sred + 256;            // [2][128]
    sred[tid] = 0.f;
    dred[tid] = 0.f;
    __syncthreads();

    float asv[4][2], adv[4][2];
#pragma unroll
    for (int nt = 0; nt < 4; nt++) {
        int col = col0 + wn * 32 + nt * 8 + ((lane & 3) << 1);
        asv[nt][0] = att_s[col];     asv[nt][1] = att_s[col + 1];
        adv[nt][0] = att_d[col];     adv[nt][1] = att_d[col + 1];
    }
#pragma unroll
    for (int mt = 0; mt < 4; mt++) {
        float s0 = 0.f, s1 = 0.f, d0 = 0.f, d1 = 0.f;
#pragma unroll
        for (int nt = 0; nt < 4; nt++) {
            s0 += c[mt][nt][0] * asv[nt][0] + c[mt][nt][1] * asv[nt][1];
            s1 += c[mt][nt][2] * asv[nt][0] + c[mt][nt][3] * asv[nt][1];
            d0 += c[mt][nt][0] * adv[nt][0] + c[mt][nt][1] * adv[nt][1];
            d1 += c[mt][nt][2] * adv[nt][0] + c[mt][nt][3] * adv[nt][1];
        }
#pragma unroll
        for (int o = 1; o <= 2; o <<= 1) {
            s0 += __shfl_xor_sync(0xffffffffu, s0, o);
            s1 += __shfl_xor_sync(0xffffffffu, s1, o);
            d0 += __shfl_xor_sync(0xffffffffu, d0, o);
            d1 += __shfl_xor_sync(0xffffffffu, d1, o);
        }
        if ((lane & 3) == 0) {
            int hh = wn >> 1;
            int rloc = wm * 64 + mt * 16 + (lane >> 2);
            atomicAdd(&sred[hh * 128 + rloc], s0);
            atomicAdd(&sred[hh * 128 + rloc + 8], s1);
            atomicAdd(&dred[hh * 128 + rloc], d0);
            atomicAdd(&dred[hh * 128 + rloc + 8], d1);
        }
    }
    __syncthreads();
    {
        int hh = tid >> 7;
        int rloc = tid & 127;
        int row = row0 + rloc;
        if (row < M) {
            int hglob = (col0 >> 6) + hh;
            out_s[row * H + hglob] = sred[hh * 128 + rloc];
            out_d[row * H + hglob] = dred[hh * 128 + rloc];
        }
    }
}

// ---------------------------------------------------------------------------
// fp32 SIMT SGEMM (layer 4 only)
// ---------------------------------------------------------------------------
__global__ void k_sgemm(const float* __restrict__ A, const float* __restrict__ B,
                        float* __restrict__ C, int M, int K, int Nn) {
    __shared__ float As[16][68];
    __shared__ float Bs[16][68];
    int tid = threadIdx.x;
    int tx = tid & 15;
    int ty = tid >> 4;
    int row0 = blockIdx.y * 64;
    int col0 = blockIdx.x * 64;

    int arow = tid >> 2;
    int acol = (tid & 3) * 4;
    int brow = tid >> 4;
    int bcol = (tid & 15) * 4;

    float acc[4][4];
#pragma unroll
    for (int i = 0; i < 4; i++)
#pragma unroll
        for (int j = 0; j < 4; j++) acc[i][j] = 0.f;

    for (int k0 = 0; k0 < K; k0 += 16) {
        float4 av = make_float4(0.f, 0.f, 0.f, 0.f);
        if (row0 + arow < M)
            av = *(const float4*)(A + (size_t)(row0 + arow) * K + k0 + acol);
        As[acol + 0][arow] = av.x;
        As[acol + 1][arow] = av.y;
        As[acol + 2][arow] = av.z;
        As[acol + 3][arow] = av.w;

        float4 bv = make_float4(0.f, 0.f, 0.f, 0.f);
        if (col0 + bcol < Nn)
            bv = *(const float4*)(B + (size_t)(k0 + brow) * Nn + col0 + bcol);
        Bs[brow][bcol + 0] = bv.x;
        Bs[brow][bcol + 1] = bv.y;
        Bs[brow][bcol + 2] = bv.z;
        Bs[brow][bcol + 3] = bv.w;
        __syncthreads();

#pragma unroll
        for (int kk = 0; kk < 16; kk++) {
            float4 a4 = *(const float4*)&As[kk][ty * 4];
            float4 b4 = *(const float4*)&Bs[kk][tx * 4];
            float a[4] = {a4.x, a4.y, a4.z, a4.w};
            float b[4] = {b4.x, b4.y, b4.z, b4.w};
#pragma unroll
            for (int i = 0; i < 4; i++)
#pragma unroll
                for (int j = 0; j < 4; j++) acc[i][j] += a[i] * b[j];
        }
        __syncthreads();
    }

#pragma unroll
    for (int i = 0; i < 4; i++) {
        int r = row0 + ty * 4 + i;
        if (r >= M) break;
#pragma unroll
        for (int j = 0; j < 4; j++) {
            int cc = col0 + tx * 4 + j;
            if (cc < Nn) C[(size_t)r * Nn + cc] = acc[i][j];
        }
    }
}

// ---------------------------------------------------------------------------
// Attention coefficients (layer 4 only)
// ---------------------------------------------------------------------------
__global__ void k_attcoef(const float* __restrict__ h, const float* __restrict__ as,
                          const float* __restrict__ ad, float* __restrict__ out_s,
                          float* __restrict__ out_d, int N, int H, int C) {
    int wid = blockIdx.x * (blockDim.x >> 5) + (threadIdx.x >> 5);
    int lane = threadIdx.x & 31;
    if (wid >= N * H) return;
    int n = wid / H;
    int hh = wid - n * H;
    int F = H * C;
    const float* hr = h + (size_t)n * F + hh * C;
    const float* asr = as + hh * C;
    const float* adr = ad + hh * C;
    float s = 0.f, d = 0.f;
    for (int c = lane; c < C; c += 32) {
        float v = hr[c];
        s += v * asr[c];
        d += v * adr[c];
    }
#pragma unroll
    for (int o = 16; o; o >>= 1) {
        s += __shfl_xor_sync(0xffffffffu, s, o);
        d += __shfl_xor_sync(0xffffffffu, d, o);
    }
    if (lane == 0) {
        out_s[wid] = s;
        out_d[wid] = d;
    }
}

// ---------------------------------------------------------------------------
// Per-node segment softmax: WARP PER NODE, all heads per lane.
// Pass 1: one src load + one vectorized a_s row read per edge; all H logits
//         computed and stored head-major. Pass 2: linear re-read, exp, sum.
// ---------------------------------------------------------------------------
template <int H>
__global__ void __launch_bounds__(256) k_attn(
    const float* __restrict__ a_s, const float* __restrict__ a_d,
    const int* __restrict__ rowptr, const int* __restrict__ srcs,
    float* __restrict__ w, float* __restrict__ invs, int N, int Etot) {
    int n = blockIdx.x * 8 + (threadIdx.x >> 5);
    if (n >= N) return;
    int lane = threadIdx.x & 31;
    int st = rowptr[n], en = rowptr[n + 1];

    float adv[H];
#pragma unroll
    for (int hh = 0; hh < H; hh++) adv[hh] = a_d[n * H + hh];

    float lmax[H];
#pragma unroll
    for (int hh = 0; hh < H; hh++) lmax[hh] = -1e30f;

    for (int i = st + lane; i < en; i += 32) {
        int src = srcs[i];
        float av[H];
        if (H == 8) {
            float4 a = *(const float4*)(a_s + src * 8);
            float4 b = *(const float4*)(a_s + src * 8 + 4);
            av[0] = a.x; av[1] = a.y; av[2] = a.z; av[3] = a.w;
            av[4] = b.x; av[5] = b.y; av[6] = b.z; av[7] = b.w;
        } else if (H == 4) {
            float4 a = *(const float4*)(a_s + src * 4);
            av[0] = a.x; av[1] = a.y; av[2] = a.z; av[3] = a.w;
        } else if (H == 2) {
            float2 a = *(const float2*)(a_s + src * 2);
            av[0] = a.x; av[1] = a.y;
        } else {
            av[0] = a_s[src];
        }
#pragma unroll
        for (int hh = 0; hh < H; hh++) {
            float v = av[hh] + adv[hh];
            v = v >= 0.f ? v : 0.2f * v;
            w[(size_t)hh * Etot + i] = v;
            lmax[hh] = fmaxf(lmax[hh], v);
        }
    }
#pragma unroll
    for (int hh = 0; hh < H; hh++) {
        float v = lmax[hh];
#pragma unroll
        for (int o = 16; o; o >>= 1) v = fmaxf(v, __shfl_xor_sync(0xffffffffu, v, o));
        lmax[hh] = v;
    }

    float lsum[H];
#pragma unroll
    for (int hh = 0; hh < H; hh++) lsum[hh] = 0.f;
    for (int i = st + lane; i < en; i += 32) {
#pragma unroll
        for (int hh = 0; hh < H; hh++) {
            float ex = __expf(w[(size_t)hh * Etot + i] - lmax[hh]);
            w[(size_t)hh * Etot + i] = ex;
            lsum[hh] += ex;
        }
    }
#pragma unroll
    for (int hh = 0; hh < H; hh++) {
        float v = lsum[hh];
#pragma unroll
        for (int o = 16; o; o >>= 1) v += __shfl_xor_sync(0xffffffffu, v, o);
        if (lane == 0) invs[n * H + hh] = 1.f / v;
    }
}

// ---------------------------------------------------------------------------
// Aggregation: block per node, float4 per thread, edge loop unrolled x8.
// ---------------------------------------------------------------------------
__global__ void k_agg(const float* __restrict__ h, const float* __restrict__ w,
                      const float* __restrict__ invs, const int* __restrict__ rowptr,
                      const int* __restrict__ srcs, const float* __restrict__ bias,
                      float* __restrict__ out, int H, int C, int F, int Etot) {
    int n = blockIdx.x;
    int f4 = threadIdx.x << 2;
    if (f4 >= F) return;
    int hh = f4 / C;
    const float* wh = w + (size_t)hh * Etot;
    int st = rowptr[n], en = rowptr[n + 1];
    float ci = invs[n * H + hh];
    float ax = 0.f, ay = 0.f, az = 0.f, aw = 0.f;

    int e = st;
    for (; e + 8 <= en; e += 8) {
        int s[8];
        float a[8];
#pragma unroll
        for (int j = 0; j < 8; j++) { s[j] = srcs[e + j]; a[j] = wh[e + j]; }
        float4 v[8];
#pragma unroll
        for (int j = 0; j < 8; j++) v[j] = *(const float4*)(h + (size_t)s[j] * F + f4);
#pragma unroll
        for (int j = 0; j < 8; j++) {
            ax += v[j].x * a[j];
            ay += v[j].y * a[j];
            az += v[j].z * a[j];
            aw += v[j].w * a[j];
        }
    }
    for (; e < en; e++) {
        int s = srcs[e];
        float a = wh[e];
        float4 v = *(const float4*)(h + (size_t)s * F + f4);
        ax += v.x * a; ay += v.y * a; az += v.z * a; aw += v.w * a;
    }
    float4 b = *(const float4*)(bias + f4);
    float4 o;
    o.x = ax * ci + b.x;
    o.y = ay * ci + b.y;
    o.z = az * ci + b.z;
    o.w = aw * ci + b.w;
    *(float4*)(out + (size_t)n * F + f4) = o;
}

// ---------------------------------------------------------------------------
// BatchNorm + ELU (optional fp32 / bf16-split stores)
// ---------------------------------------------------------------------------
__global__ void k_zero_f2(float* a, float* b, int n) {
    int i = blockIdx.x * blockDim.x + threadIdx.x;
    if (i < n) { a[i] = 0.f; b[i] = 0.f; }
}

__global__ void k_bnstats(const float* __restrict__ x, float* __restrict__ csum,
                          float* __restrict__ csq, int N, int F) {
    int c = threadIdx.x;
    float s = 0.f, sq = 0.f;
    for (int r = blockIdx.x; r < N; r += gridDim.x) {
        float v = x[(size_t)r * F + c];
        s += v;
        sq += v * v;
    }
    atomicAdd(&csum[c], s);
    atomicAdd(&csq[c], sq);
}

__global__ void k_bnapply_split(const float* __restrict__ in, float* __restrict__ out,
                                __nv_bfloat16* __restrict__ hi, __nv_bfloat16* __restrict__ lo,
                                const float* __restrict__ csum, const float* __restrict__ csq,
                                const float* __restrict__ gamma, const float* __restrict__ beta,
                                int N, int F, int store_f32, int store_bf16) {
    int idx = blockIdx.x * blockDim.x + threadIdx.x;
    if (idx >= N * F) return;
    int c = idx % F;
    float invN = 1.f / (float)N;
    float mean = csum[c] * invN;
    float var = csq[c] * invN - mean * mean;
    float v = (in[idx] - mean) * rsqrtf(var + 1e-5f) * gamma[c] + beta[c];
    v = v > 0.f ? v : (__expf(v) - 1.f);
    if (store_f32) out[idx] = v;
    if (store_bf16) {
        __nv_bfloat16 h = __float2bfloat16(v);
        hi[idx] = h;
        lo[idx] = __float2bfloat16(v - __bfloat162float(h));
    }
}

// ---------------------------------------------------------------------------
// log_softmax over 16 classes
// ---------------------------------------------------------------------------
__global__ void k_logsoftmax16(const float* __restrict__ in, float* __restrict__ out, int N) {
    int n = blockIdx.x * blockDim.x + threadIdx.x;
    if (n >= N) return;
    const float* r = in + n * 16;
    float mx = r[0];
#pragma unroll
    for (int j = 1; j < 16; j++) mx = fmaxf(mx, r[j]);
    float s = 0.f;
#pragma unroll
    for (int j = 0; j < 16; j++) s += __expf(r[j] - mx);
    float ls = logf(s) + mx;
    float* o = out + n * 16;
#pragma unroll
    for (int j = 0; j < 16; j++) o[j] = r[j] - ls;
}

// ---------------------------------------------------------------------------
// Host orchestration
// ---------------------------------------------------------------------------
extern "C" void kernel_launch(void* const* d_in, const int* in_sizes, int n_in,
                              void* d_out, int out_size) {
    const float* x = (const float*)d_in[0];
    const int* ei = (const int*)d_in[1];
    int N = in_sizes[0] / 512;
    int E = in_sizes[1] / 2;
    int Etot = E + N;

    float *p_h, *p_y, *p_agg, *p_as, *p_ad, *p_w, *p_invs, *p_csum, *p_csq;
    int *p_deg, *p_rowptr, *p_cursor, *p_srcs, *p_bsums;
    __nv_bfloat16 *p_ahi, *p_alo, *p_bhi, *p_blo;
    cudaGetSymbolAddress((void**)&p_h, g_h);
    cudaGetSymbolAddress((void**)&p_y, g_y);
    cudaGetSymbolAddress((void**)&p_agg, g_agg);
    cudaGetSymbolAddress((void**)&p_as, g_as);
    cudaGetSymbolAddress((void**)&p_ad, g_ad);
    cudaGetSymbolAddress((void**)&p_w, g_w);
    cudaGetSymbolAddress((void**)&p_invs, g_invs);
    cudaGetSymbolAddress((void**)&p_csum, g_colsum);
    cudaGetSymbolAddress((void**)&p_csq, g_colsq);
    cudaGetSymbolAddress((void**)&p_deg, g_deg);
    cudaGetSymbolAddress((void**)&p_rowptr, g_rowptr);
    cudaGetSymbolAddress((void**)&p_cursor, g_cursor);
    cudaGetSymbolAddress((void**)&p_srcs, g_srcs);
    cudaGetSymbolAddress((void**)&p_bsums, g_bsums);
    cudaGetSymbolAddress((void**)&p_ahi, g_ahi);
    cudaGetSymbolAddress((void**)&p_alo, g_alo);
    cudaGetSymbolAddress((void**)&p_bhi, g_bhi);
    cudaGetSymbolAddress((void**)&p_blo, g_blo);

    cudaFuncSetAttribute(k_mma_gemm, cudaFuncAttributeMaxDynamicSharedMemorySize, MMA_SMEM);

    struct Cfg { int Fin, H, C, iW; bool bn; };
    const Cfg cfgs[4] = {
        {512, 8, 64, 2, true},
        {512, 4, 64, 8, true},
        {256, 2, 64, 14, true},
        {128, 1, 16, 20, false},
    };

    // ---- Layer-1 prep + GEMM ----
    {
        int nel = N * 512;
        k_zero_int<<<(N + 255) / 256, 256>>>(p_deg, N);
        k_split<<<(nel / 4 + 255) / 256, 256>>>(x, p_ahi, p_alo, nel);
        int nw = 512 * 512;
        k_split<<<(nw / 4 + 255) / 256, 256>>>((const float*)d_in[2], p_bhi, p_blo, nw);
        dim3 gg(512 / 128, (N + 127) / 128);
        k_mma_gemm<<<gg, 256, MMA_SMEM>>>(p_ahi, p_alo, p_bhi, p_blo, p_h, N, 512, 512,
                                          (const float*)d_in[3], (const float*)d_in[4],
                                          p_as, p_ad, 8);
    }

    // ---- CSR build ----
    k_hist<<<(Etot + 255) / 256, 256>>>(ei, E, N, p_deg);
    int nblk = (N + SCAN_B - 1) / SCAN_B;
    k_scan1<<<nblk, SCAN_B>>>(p_deg, p_rowptr, p_bsums, N);
    k_scan2<<<1, 32>>>(p_bsums, nblk);
    k_scan3<<<(N + 255) / 256, 256>>>(p_rowptr, p_bsums, N, Etot, p_cursor);
    k_scatter<<<(Etot + 255) / 256, 256>>>(ei, E, N, p_cursor, p_srcs);

    const float* in = x;
    int nwarpblk = (N + 7) / 8;
    for (int li = 0; li < 4; li++) {
        const Cfg& cf = cfgs[li];
        int F = cf.H * cf.C;
        const float* W  = (const float*)d_in[cf.iW + 0];
        const float* as = (const float*)d_in[cf.iW + 1];
        const float* ad = (const float*)d_in[cf.iW + 2];
        const float* bi = (const float*)d_in[cf.iW + 3];

        if (li >= 1 && li < 3) {
            int nw = cf.Fin * F;
            k_split<<<(nw / 4 + 255) / 256, 256>>>(W, p_bhi, p_blo, nw);
            dim3 gg(F / 128, (N + 127) / 128);
            k_mma_gemm<<<gg, 256, MMA_SMEM>>>(p_ahi, p_alo, p_bhi, p_blo, p_h, N, cf.Fin, F,
                                              as, ad, p_as, p_ad, cf.H);
        } else if (li == 3) {
            dim3 ggrid((F + 63) / 64, (N + 63) / 64);
            k_sgemm<<<ggrid, 256>>>(in, W, p_h, N, cf.Fin, F);
            int pairs = N * cf.H;
            k_attcoef<<<(pairs + 3) / 4, 128>>>(p_h, as, ad, p_as, p_ad, N, cf.H, cf.C);
        }

        switch (cf.H) {
            case 8: k_attn<8><<<nwarpblk, 256>>>(p_as, p_ad, p_rowptr, p_srcs, p_w, p_invs, N, Etot); break;
            case 4: k_attn<4><<<nwarpblk, 256>>>(p_as, p_ad, p_rowptr, p_srcs, p_w, p_invs, N, Etot); break;
            case 2: k_attn<2><<<nwarpblk, 256>>>(p_as, p_ad, p_rowptr, p_srcs, p_w, p_invs, N, Etot); break;
            default: k_attn<1><<<nwarpblk, 256>>>(p_as, p_ad, p_rowptr, p_srcs, p_w, p_invs, N, Etot); break;
        }

        int T = (F >= 128) ? (F >> 2) : 32;
        k_agg<<<N, T>>>(p_h, p_w, p_invs, p_rowptr, p_srcs, bi, p_agg, cf.H, cf.C, F, Etot);

        if (cf.bn) {
            const float* gamma = (const float*)d_in[cf.iW + 4];
            const float* beta  = (const float*)d_in[cf.iW + 5];
            k_zero_f2<<<1, F>>>(p_csum, p_csq, F);
            k_bnstats<<<240, F>>>(p_agg, p_csum, p_csq, N, F);
            int store_f32 = (li == 2) ? 1 : 0;   // only layer-3 output read as fp32 (by L4 sgemm)
            int store_bf16 = (li < 2) ? 1 : 0;   // only layers 1-2 feed MMA GEMMs
            k_bnapply_split<<<(N * F + 255) / 256, 256>>>(p_agg, p_y, p_ahi, p_alo,
                                                          p_csum, p_csq, gamma, beta, N, F,
                                                          store_f32, store_bf16);
            in = p_y;
        } else {
            k_logsoftmax16<<<(N + 255) / 256, 256>>>(p_agg, (float*)d_out, N);
        }
    }
}

// round 9
// speedup vs baseline: 1.1217x; 1.0153x over previous
#include <cuda_runtime.h>
#include <cuda_bf16.h>
#include <cstdint>
#include <math.h>

// ---------------------------------------------------------------------------
// GAT 4-layer network. (R8 structure + fused warp-per-node layer-4 tail)
//   - CSR build (dst-sorted) once per call
//   - Layers 1-3: split-bf16 HMMA GEMM (mma.sync m16n8k16), 3-stage cp.async
//     pipeline, fused attention-coefficient epilogue.
//   - Layer 4: fp32 SIMT GEMM + attcoef, then ONE warp-per-node kernel doing
//     softmax + aggregation + bias + log_softmax entirely in registers.
//   - k_attn: warp per node, all heads per lane; k_agg: block per node.
//   - BN+ELU with per-layer dead-store elision.
// ---------------------------------------------------------------------------

#define MAXN 20000
#define MAXE 360000
#define MAXF 512
#define MAXH 8
#define SCAN_B 512

__device__ float g_h[MAXN * MAXF];
__device__ float g_y[MAXN * MAXF];
__device__ float g_agg[MAXN * MAXF];
__device__ float g_as[MAXN * MAXH];
__device__ float g_ad[MAXN * MAXH];
__device__ float g_w[MAXE * MAXH];     // head-major: [H][Etot]
__device__ float g_invs[MAXN * MAXH];
__device__ int   g_deg[MAXN];
__device__ int   g_rowptr[MAXN + 1];
__device__ int   g_cursor[MAXN];
__device__ int   g_srcs[MAXE];
__device__ float g_colsum[MAXF];
__device__ float g_colsq[MAXF];
__device__ int   g_bsums[64];
__device__ __nv_bfloat16 g_ahi[MAXN * MAXF];
__device__ __nv_bfloat16 g_alo[MAXN * MAXF];
__device__ __nv_bfloat16 g_bhi[MAXF * MAXF];
__device__ __nv_bfloat16 g_blo[MAXF * MAXF];

// ---------------------------------------------------------------------------
// PTX helpers
// ---------------------------------------------------------------------------
__device__ __forceinline__ uint32_t smem_to_u32(const void* p) {
    uint32_t a;
    asm("{ .reg .u64 t; cvta.to.shared.u64 t, %1; cvt.u32.u64 %0, t; }" : "=r"(a) : "l"(p));
    return a;
}
__device__ __forceinline__ void cp16(uint32_t s, const void* g) {
    asm volatile("cp.async.cg.shared.global [%0], [%1], 16;" :: "r"(s), "l"(g));
}
__device__ __forceinline__ void ldsm_x4(uint32_t* r, uint32_t addr) {
    asm volatile("ldmatrix.sync.aligned.m8n8.x4.shared.b16 {%0,%1,%2,%3}, [%4];"
        : "=r"(r[0]), "=r"(r[1]), "=r"(r[2]), "=r"(r[3]) : "r"(addr));
}
__device__ __forceinline__ void ldsm_x4_t(uint32_t* r, uint32_t addr) {
    asm volatile("ldmatrix.sync.aligned.m8n8.x4.trans.shared.b16 {%0,%1,%2,%3}, [%4];"
        : "=r"(r[0]), "=r"(r[1]), "=r"(r[2]), "=r"(r[3]) : "r"(addr));
}
__device__ __forceinline__ void mma16816(float* c, const uint32_t* a, const uint32_t* b) {
    asm volatile("mma.sync.aligned.m16n8k16.row.col.f32.bf16.bf16.f32 "
        "{%0,%1,%2,%3}, {%4,%5,%6,%7}, {%8,%9}, {%0,%1,%2,%3};"
        : "+f"(c[0]), "+f"(c[1]), "+f"(c[2]), "+f"(c[3])
        : "r"(a[0]), "r"(a[1]), "r"(a[2]), "r"(a[3]), "r"(b[0]), "r"(b[1]));
}

// ---------------------------------------------------------------------------
// CSR build
// ---------------------------------------------------------------------------
__global__ void k_zero_int(int* p, int n) {
    int i = blockIdx.x * blockDim.x + threadIdx.x;
    if (i < n) p[i] = 0;
}

__global__ void k_hist(const int* __restrict__ ei, int E, int N, int* __restrict__ deg) {
    int e = blockIdx.x * blockDim.x + threadIdx.x;
    if (e >= E + N) return;
    int dst = (e < E) ? ei[E + e] : (e - E);
    atomicAdd(&deg[dst], 1);
}

__global__ void k_scan1(const int* __restrict__ deg, int* __restrict__ rowptr,
                        int* __restrict__ bsums, int n) {
    __shared__ int sh[SCAN_B];
    int i = blockIdx.x * SCAN_B + threadIdx.x;
    int v = (i < n) ? deg[i] : 0;
    sh[threadIdx.x] = v;
    __syncthreads();
    for (int off = 1; off < SCAN_B; off <<= 1) {
        int t = 0;
        if ((int)threadIdx.x >= off) t = sh[threadIdx.x - off];
        __syncthreads();
        sh[threadIdx.x] += t;
        __syncthreads();
    }
    if (i < n) rowptr[i] = sh[threadIdx.x] - v;
    if (threadIdx.x == SCAN_B - 1) bsums[blockIdx.x] = sh[SCAN_B - 1];
}

__global__ void k_scan2(int* bsums, int nb) {
    if (threadIdx.x == 0) {
        int run = 0;
        for (int i = 0; i < nb; i++) { int v = bsums[i]; bsums[i] = run; run += v; }
    }
}

__global__ void k_scan3(int* __restrict__ rowptr, const int* __restrict__ bsums,
                        int n, int etot, int* __restrict__ cursor) {
    int i = blockIdx.x * blockDim.x + threadIdx.x;
    if (i < n) {
        int v = rowptr[i] + bsums[i / SCAN_B];
        rowptr[i] = v;
        cursor[i] = v;
    }
    if (i == 0) rowptr[n] = etot;
}

__global__ void k_scatter(const int* __restrict__ ei, int E, int N,
                          int* __restrict__ cursor, int* __restrict__ srcs) {
    int e = blockIdx.x * blockDim.x + threadIdx.x;
    if (e >= E + N) return;
    int src, dst;
    if (e < E) { src = ei[e]; dst = ei[E + e]; }
    else       { src = dst = e - E; }
    int p = atomicAdd(&cursor[dst], 1);
    srcs[p] = src;
}

// ---------------------------------------------------------------------------
// fp32 -> (bf16 hi, bf16 lo) split
// ---------------------------------------------------------------------------
__global__ void k_split(const float* __restrict__ x, __nv_bfloat16* __restrict__ hi,
                        __nv_bfloat16* __restrict__ lo, int n) {
    int i = (blockIdx.x * blockDim.x + threadIdx.x) * 4;
    if (i >= n) return;
    float4 v = *(const float4*)(x + i);
    __nv_bfloat16 h0 = __float2bfloat16(v.x), h1 = __float2bfloat16(v.y);
    __nv_bfloat16 h2 = __float2bfloat16(v.z), h3 = __float2bfloat16(v.w);
    __nv_bfloat16 l0 = __float2bfloat16(v.x - __bfloat162float(h0));
    __nv_bfloat16 l1 = __float2bfloat16(v.y - __bfloat162float(h1));
    __nv_bfloat16 l2 = __float2bfloat16(v.z - __bfloat162float(h2));
    __nv_bfloat16 l3 = __float2bfloat16(v.w - __bfloat162float(h3));
    __nv_bfloat162* ph = (__nv_bfloat162*)(hi + i);
    __nv_bfloat162* pl = (__nv_bfloat162*)(lo + i);
    ph[0] = __nv_bfloat162(h0, h1); ph[1] = __nv_bfloat162(h2, h3);
    pl[0] = __nv_bfloat162(l0, l1); pl[1] = __nv_bfloat162(l2, l3);
}

// ---------------------------------------------------------------------------
// split-bf16 HMMA GEMM + fused attention coefficients
// ---------------------------------------------------------------------------
#define STAGE_BYTES 37888
#define OFF_ALO 10240
#define OFF_BHI 20480
#define OFF_BLO 29184
#define MMA_SMEM (3 * STAGE_BYTES)

__global__ void __launch_bounds__(256, 2) k_mma_gemm(
    const __nv_bfloat16* __restrict__ Ahi, const __nv_bfloat16* __restrict__ Alo,
    const __nv_bfloat16* __restrict__ Bhi, const __nv_bfloat16* __restrict__ Blo,
    float* __restrict__ C, int M, int K, int Nn,
    const float* __restrict__ att_s, const float* __restrict__ att_d,
    float* __restrict__ out_s, float* __restrict__ out_d, int H) {
    extern __shared__ char smem[];
    uint32_t sbu = smem_to_u32(smem);
    int tid = threadIdx.x, lane = tid & 31, wid = tid >> 5;
    int wm = wid & 1, wn = wid >> 1;
    int row0 = blockIdx.y * 128, col0 = blockIdx.x * 128;

    float c[4][4][4];
#pragma unroll
    for (int i = 0; i < 4; i++)
#pragma unroll
        for (int j = 0; j < 4; j++) {
            c[i][j][0] = 0.f; c[i][j][1] = 0.f; c[i][j][2] = 0.f; c[i][j][3] = 0.f;
        }

    int nch = K >> 5;

    auto issue = [&](int ch) {
        uint32_t sb = sbu + (uint32_t)(ch % 3) * STAGE_BYTES;
        int k0 = ch << 5;
#pragma unroll
        for (int i = 0; i < 2; i++) {
            int g = tid + i * 256;
            int r = g >> 2, c8 = (g & 3) << 3;
            int row = row0 + r;
            if (row >= M) row = M - 1;
            size_t ga = (size_t)row * K + k0 + c8;
            uint32_t sa = sb + r * 80 + (c8 << 1);
            cp16(sa, Ahi + ga);
            cp16(sa + OFF_ALO, Alo + ga);
            int rb = g >> 4, cb = (g & 15) << 3;
            size_t gb = (size_t)(k0 + rb) * Nn + col0 + cb;
            uint32_t sB = sb + OFF_BHI + rb * 272 + (cb << 1);
            cp16(sB, Bhi + gb);
            cp16(sB + (OFF_BLO - OFF_BHI), Blo + gb);
        }
        asm volatile("cp.async.commit_group;" ::: "memory");
    };

    issue(0);
    issue(1);
    for (int ch = 0; ch < nch; ch++) {
        if (ch + 1 < nch)
            asm volatile("cp.async.wait_group 1;" ::: "memory");
        else
            asm volatile("cp.async.wait_group 0;" ::: "memory");
        __syncthreads();
        if (ch + 2 < nch) issue(ch + 2);

        uint32_t sb = sbu + (uint32_t)(ch % 3) * STAGE_BYTES;
#pragma unroll
        for (int kk2 = 0; kk2 < 2; kk2++) {
            int kk = kk2 << 4;
            uint32_t ah[4][4], al[4][4], bh[2][4], bl[2][4];
#pragma unroll
            for (int mt = 0; mt < 4; mt++) {
                uint32_t aoff = sb + (uint32_t)(wm * 64 + mt * 16 + (lane & 15)) * 80
                              + ((kk + ((lane >> 4) << 3)) << 1);
                ldsm_x4(ah[mt], aoff);
                ldsm_x4(al[mt], aoff + OFF_ALO);
            }
#pragma unroll
            for (int nt2 = 0; nt2 < 2; nt2++) {
                uint32_t boff = sb + OFF_BHI + (uint32_t)(kk + (lane & 15)) * 272
                              + ((wn * 32 + nt2 * 16 + ((lane >> 4) << 3)) << 1);
                ldsm_x4_t(bh[nt2], boff);
                ldsm_x4_t(bl[nt2], boff + (OFF_BLO - OFF_BHI));
            }
#pragma unroll
            for (int mt = 0; mt < 4; mt++)
#pragma unroll
                for (int nt = 0; nt < 4; nt++)
                    mma16816(c[mt][nt], ah[mt], &bh[nt >> 1][(nt & 1) << 1]);
#pragma unroll
            for (int mt = 0; mt < 4; mt++)
#pragma unroll
                for (int nt = 0; nt < 4; nt++)
                    mma16816(c[mt][nt], ah[mt], &bl[nt >> 1][(nt & 1) << 1]);
#pragma unroll
            for (int mt = 0; mt < 4; mt++)
#pragma unroll
                for (int nt = 0; nt < 4; nt++)
                    mma16816(c[mt][nt], al[mt], &bh[nt >> 1][(nt & 1) << 1]);
        }
    }

    // ---- C store ----
#pragma unroll
    for (int mt = 0; mt < 4; mt++) {
        int r = row0 + wm * 64 + mt * 16 + (lane >> 2);
#pragma unroll
        for (int nt = 0; nt < 4; nt++) {
            int col = col0 + wn * 32 + nt * 8 + ((lane & 3) << 1);
            if (r < M) {
                float2 v = make_float2(c[mt][nt][0], c[mt][nt][1]);
                *(float2*)(C + (size_t)r * Nn + col) = v;
            }
            if (r + 8 < M) {
                float2 v = make_float2(c[mt][nt][2], c[mt][nt][3]);
                *(float2*)(C + (size_t)(r + 8) * Nn + col) = v;
            }
        }
    }

    // ---- fused attention coefficients ----
    __syncthreads();
    float* sred = (float*)smem;          // [2][128]
    float* dred = sred + 256;            // [2][128]
    sred[tid] = 0.f;
    dred[tid] = 0.f;
    __syncthreads();

    float asv[4][2], adv[4][2];
#pragma unroll
    for (int nt = 0; nt < 4; nt++) {
        int col = col0 + wn * 32 + nt * 8 + ((lane & 3) << 1);
        asv[nt][0] = att_s[col];     asv[nt][1] = att_s[col + 1];
        adv[nt][0] = att_d[col];     adv[nt][1] = att_d[col + 1];
    }
#pragma unroll
    for (int mt = 0; mt < 4; mt++) {
        float s0 = 0.f, s1 = 0.f, d0 = 0.f, d1 = 0.f;
#pragma unroll
        for (int nt = 0; nt < 4; nt++) {
            s0 += c[mt][nt][0] * asv[nt][0] + c[mt][nt][1] * asv[nt][1];
            s1 += c[mt][nt][2] * asv[nt][0] + c[mt][nt][3] * asv[nt][1];
            d0 += c[mt][nt][0] * adv[nt][0] + c[mt][nt][1] * adv[nt][1];
            d1 += c[mt][nt][2] * adv[nt][0] + c[mt][nt][3] * adv[nt][1];
        }
#pragma unroll
        for (int o = 1; o <= 2; o <<= 1) {
            s0 += __shfl_xor_sync(0xffffffffu, s0, o);
            s1 += __shfl_xor_sync(0xffffffffu, s1, o);
            d0 += __shfl_xor_sync(0xffffffffu, d0, o);
            d1 += __shfl_xor_sync(0xffffffffu, d1, o);
        }
        if ((lane & 3) == 0) {
            int hh = wn >> 1;
            int rloc = wm * 64 + mt * 16 + (lane >> 2);
            atomicAdd(&sred[hh * 128 + rloc], s0);
            atomicAdd(&sred[hh * 128 + rloc + 8], s1);
            atomicAdd(&dred[hh * 128 + rloc], d0);
            atomicAdd(&dred[hh * 128 + rloc + 8], d1);
        }
    }
    __syncthreads();
    {
        int hh = tid >> 7;
        int rloc = tid & 127;
        int row = row0 + rloc;
        if (row < M) {
            int hglob = (col0 >> 6) + hh;
            out_s[row * H + hglob] = sred[hh * 128 + rloc];
            out_d[row * H + hglob] = dred[hh * 128 + rloc];
        }
    }
}

// ---------------------------------------------------------------------------
// fp32 SIMT SGEMM (layer 4 only)
// ---------------------------------------------------------------------------
__global__ void k_sgemm(const float* __restrict__ A, const float* __restrict__ B,
                        float* __restrict__ C, int M, int K, int Nn) {
    __shared__ float As[16][68];
    __shared__ float Bs[16][68];
    int tid = threadIdx.x;
    int tx = tid & 15;
    int ty = tid >> 4;
    int row0 = blockIdx.y * 64;
    int col0 = blockIdx.x * 64;

    int arow = tid >> 2;
    int acol = (tid & 3) * 4;
    int brow = tid >> 4;
    int bcol = (tid & 15) * 4;

    float acc[4][4];
#pragma unroll
    for (int i = 0; i < 4; i++)
#pragma unroll
        for (int j = 0; j < 4; j++) acc[i][j] = 0.f;

    for (int k0 = 0; k0 < K; k0 += 16) {
        float4 av = make_float4(0.f, 0.f, 0.f, 0.f);
        if (row0 + arow < M)
            av = *(const float4*)(A + (size_t)(row0 + arow) * K + k0 + acol);
        As[acol + 0][arow] = av.x;
        As[acol + 1][arow] = av.y;
        As[acol + 2][arow] = av.z;
        As[acol + 3][arow] = av.w;

        float4 bv = make_float4(0.f, 0.f, 0.f, 0.f);
        if (col0 + bcol < Nn)
            bv = *(const float4*)(B + (size_t)(k0 + brow) * Nn + col0 + bcol);
        Bs[brow][bcol + 0] = bv.x;
        Bs[brow][bcol + 1] = bv.y;
        Bs[brow][bcol + 2] = bv.z;
        Bs[brow][bcol + 3] = bv.w;
        __syncthreads();

#pragma unroll
        for (int kk = 0; kk < 16; kk++) {
            float4 a4 = *(const float4*)&As[kk][ty * 4];
            float4 b4 = *(const float4*)&Bs[kk][tx * 4];
            float a[4] = {a4.x, a4.y, a4.z, a4.w};
            float b[4] = {b4.x, b4.y, b4.z, b4.w};
#pragma unroll
            for (int i = 0; i < 4; i++)
#pragma unroll
                for (int j = 0; j < 4; j++) acc[i][j] += a[i] * b[j];
        }
        __syncthreads();
    }

#pragma unroll
    for (int i = 0; i < 4; i++) {
        int r = row0 + ty * 4 + i;
        if (r >= M) break;
#pragma unroll
        for (int j = 0; j < 4; j++) {
            int cc = col0 + tx * 4 + j;
            if (cc < Nn) C[(size_t)r * Nn + cc] = acc[i][j];
        }
    }
}

// ---------------------------------------------------------------------------
// Attention coefficients (layer 4 only)
// ---------------------------------------------------------------------------
__global__ void k_attcoef(const float* __restrict__ h, const float* __restrict__ as,
                          const float* __restrict__ ad, float* __restrict__ out_s,
                          float* __restrict__ out_d, int N, int H, int C) {
    int wid = blockIdx.x * (blockDim.x >> 5) + (threadIdx.x >> 5);
    int lane = threadIdx.x & 31;
    if (wid >= N * H) return;
    int n = wid / H;
    int hh = wid - n * H;
    int F = H * C;
    const float* hr = h + (size_t)n * F + hh * C;
    const float* asr = as + hh * C;
    const float* adr = ad + hh * C;
    float s = 0.f, d = 0.f;
    for (int c = lane; c < C; c += 32) {
        float v = hr[c];
        s += v * asr[c];
        d += v * adr[c];
    }
#pragma unroll
    for (int o = 16; o; o >>= 1) {
        s += __shfl_xor_sync(0xffffffffu, s, o);
        d += __shfl_xor_sync(0xffffffffu, d, o);
    }
    if (lane == 0) {
        out_s[wid] = s;
        out_d[wid] = d;
    }
}

// ---------------------------------------------------------------------------
// Per-node segment softmax: warp per node, all heads per lane (layers 1-3)
// ---------------------------------------------------------------------------
template <int H>
__global__ void __launch_bounds__(256) k_attn(
    const float* __restrict__ a_s, const float* __restrict__ a_d,
    const int* __restrict__ rowptr, const int* __restrict__ srcs,
    float* __restrict__ w, float* __restrict__ invs, int N, int Etot) {
    int n = blockIdx.x * 8 + (threadIdx.x >> 5);
    if (n >= N) return;
    int lane = threadIdx.x & 31;
    int st = rowptr[n], en = rowptr[n + 1];

    float adv[H];
#pragma unroll
    for (int hh = 0; hh < H; hh++) adv[hh] = a_d[n * H + hh];

    float lmax[H];
#pragma unroll
    for (int hh = 0; hh < H; hh++) lmax[hh] = -1e30f;

    for (int i = st + lane; i < en; i += 32) {
        int src = srcs[i];
        float av[H];
        if (H == 8) {
            float4 a = *(const float4*)(a_s + src * 8);
            float4 b = *(const float4*)(a_s + src * 8 + 4);
            av[0] = a.x; av[1] = a.y; av[2] = a.z; av[3] = a.w;
            av[4] = b.x; av[5] = b.y; av[6] = b.z; av[7] = b.w;
        } else if (H == 4) {
            float4 a = *(const float4*)(a_s + src * 4);
            av[0] = a.x; av[1] = a.y; av[2] = a.z; av[3] = a.w;
        } else {
            float2 a = *(const float2*)(a_s + src * 2);
            av[0] = a.x; av[1] = a.y;
        }
#pragma unroll
        for (int hh = 0; hh < H; hh++) {
            float v = av[hh] + adv[hh];
            v = v >= 0.f ? v : 0.2f * v;
            w[(size_t)hh * Etot + i] = v;
            lmax[hh] = fmaxf(lmax[hh], v);
        }
    }
#pragma unroll
    for (int hh = 0; hh < H; hh++) {
        float v = lmax[hh];
#pragma unroll
        for (int o = 16; o; o >>= 1) v = fmaxf(v, __shfl_xor_sync(0xffffffffu, v, o));
        lmax[hh] = v;
    }

    float lsum[H];
#pragma unroll
    for (int hh = 0; hh < H; hh++) lsum[hh] = 0.f;
    for (int i = st + lane; i < en; i += 32) {
#pragma unroll
        for (int hh = 0; hh < H; hh++) {
            float ex = __expf(w[(size_t)hh * Etot + i] - lmax[hh]);
            w[(size_t)hh * Etot + i] = ex;
            lsum[hh] += ex;
        }
    }
#pragma unroll
    for (int hh = 0; hh < H; hh++) {
        float v = lsum[hh];
#pragma unroll
        for (int o = 16; o; o >>= 1) v += __shfl_xor_sync(0xffffffffu, v, o);
        if (lane == 0) invs[n * H + hh] = 1.f / v;
    }
}

// ---------------------------------------------------------------------------
// Aggregation: block per node, float4 per thread, edge loop unrolled x8.
// (layers 1-3)
// ---------------------------------------------------------------------------
__global__ void k_agg(const float* __restrict__ h, const float* __restrict__ w,
                      const float* __restrict__ invs, const int* __restrict__ rowptr,
                      const int* __restrict__ srcs, const float* __restrict__ bias,
                      float* __restrict__ out, int H, int C, int F, int Etot) {
    int n = blockIdx.x;
    int f4 = threadIdx.x << 2;
    if (f4 >= F) return;
    int hh = f4 / C;
    const float* wh = w + (size_t)hh * Etot;
    int st = rowptr[n], en = rowptr[n + 1];
    float ci = invs[n * H + hh];
    float ax = 0.f, ay = 0.f, az = 0.f, aw = 0.f;

    int e = st;
    for (; e + 8 <= en; e += 8) {
        int s[8];
        float a[8];
#pragma unroll
        for (int j = 0; j < 8; j++) { s[j] = srcs[e + j]; a[j] = wh[e + j]; }
        float4 v[8];
#pragma unroll
        for (int j = 0; j < 8; j++) v[j] = *(const float4*)(h + (size_t)s[j] * F + f4);
#pragma unroll
        for (int j = 0; j < 8; j++) {
            ax += v[j].x * a[j];
            ay += v[j].y * a[j];
            az += v[j].z * a[j];
            aw += v[j].w * a[j];
        }
    }
    for (; e < en; e++) {
        int s = srcs[e];
        float a = wh[e];
        float4 v = *(const float4*)(h + (size_t)s * F + f4);
        ax += v.x * a; ay += v.y * a; az += v.z * a; aw += v.w * a;
    }
    float4 b = *(const float4*)(bias + f4);
    float4 o;
    o.x = ax * ci + b.x;
    o.y = ay * ci + b.y;
    o.z = az * ci + b.z;
    o.w = aw * ci + b.w;
    *(float4*)(out + (size_t)n * F + f4) = o;
}

// ---------------------------------------------------------------------------
// Layer-4 fused tail: warp per node; softmax (H=1) + aggregation (F=16)
// + bias + log_softmax, all in registers. Recompute-based softmax (no w buf).
// ---------------------------------------------------------------------------
__global__ void __launch_bounds__(256) k_l4_tail(
    const float* __restrict__ h, const float* __restrict__ a_s,
    const float* __restrict__ a_d, const int* __restrict__ rowptr,
    const int* __restrict__ srcs, const float* __restrict__ bias,
    float* __restrict__ out, int N) {
    int n = blockIdx.x * 8 + (threadIdx.x >> 5);
    if (n >= N) return;
    int lane = threadIdx.x & 31;
    int st = rowptr[n], en = rowptr[n + 1];
    float adv = a_d[n];

    // pass 1: max of leaky-relu logits
    float mx = -1e30f;
    for (int i = st + lane; i < en; i += 32) {
        float v = a_s[srcs[i]] + adv;
        v = v >= 0.f ? v : 0.2f * v;
        mx = fmaxf(mx, v);
    }
#pragma unroll
    for (int o = 16; o; o >>= 1) mx = fmaxf(mx, __shfl_xor_sync(0xffffffffu, mx, o));

    // pass 2: weighted feature aggregation + weight sum (one gather pass)
    float sum = 0.f;
    float4 acc0 = make_float4(0.f, 0.f, 0.f, 0.f);
    float4 acc1 = make_float4(0.f, 0.f, 0.f, 0.f);
    float4 acc2 = make_float4(0.f, 0.f, 0.f, 0.f);
    float4 acc3 = make_float4(0.f, 0.f, 0.f, 0.f);
    for (int i = st + lane; i < en; i += 32) {
        int src = srcs[i];
        float v = a_s[src] + adv;
        v = v >= 0.f ? v : 0.2f * v;
        float ex = __expf(v - mx);
        sum += ex;
        const float4* hr = (const float4*)(h + (size_t)src * 16);
        float4 r0 = hr[0], r1 = hr[1], r2 = hr[2], r3 = hr[3];
        acc0.x += r0.x * ex; acc0.y += r0.y * ex; acc0.z += r0.z * ex; acc0.w += r0.w * ex;
        acc1.x += r1.x * ex; acc1.y += r1.y * ex; acc1.z += r1.z * ex; acc1.w += r1.w * ex;
        acc2.x += r2.x * ex; acc2.y += r2.y * ex; acc2.z += r2.z * ex; acc2.w += r2.w * ex;
        acc3.x += r3.x * ex; acc3.y += r3.y * ex; acc3.z += r3.z * ex; acc3.w += r3.w * ex;
    }
    // warp-reduce sum and the 16 accumulators
    float f[16] = {acc0.x, acc0.y, acc0.z, acc0.w, acc1.x, acc1.y, acc1.z, acc1.w,
                   acc2.x, acc2.y, acc2.z, acc2.w, acc3.x, acc3.y, acc3.z, acc3.w};
#pragma unroll
    for (int o = 16; o; o >>= 1) {
        sum += __shfl_xor_sync(0xffffffffu, sum, o);
#pragma unroll
        for (int j = 0; j < 16; j++) f[j] += __shfl_xor_sync(0xffffffffu, f[j], o);
    }
    float inv = 1.f / sum;
#pragma unroll
    for (int j = 0; j < 16; j++) f[j] = f[j] * inv + bias[j];

    // log_softmax over the 16 values (every lane has full row)
    float m16 = f[0];
#pragma unroll
    for (int j = 1; j < 16; j++) m16 = fmaxf(m16, f[j]);
    float s16 = 0.f;
#pragma unroll
    for (int j = 0; j < 16; j++) s16 += __expf(f[j] - m16);
    float ls = logf(s16) + m16;
    if (lane < 16) out[n * 16 + lane] = f[lane] - ls;
}

// ---------------------------------------------------------------------------
// BatchNorm + ELU (optional fp32 / bf16-split stores)
// ---------------------------------------------------------------------------
__global__ void k_zero_f2(float* a, float* b, int n) {
    int i = blockIdx.x * blockDim.x + threadIdx.x;
    if (i < n) { a[i] = 0.f; b[i] = 0.f; }
}

__global__ void k_bnstats(const float* __restrict__ x, float* __restrict__ csum,
                          float* __restrict__ csq, int N, int F) {
    int c = threadIdx.x;
    float s = 0.f, sq = 0.f;
    for (int r = blockIdx.x; r < N; r += gridDim.x) {
        float v = x[(size_t)r * F + c];
        s += v;
        sq += v * v;
    }
    atomicAdd(&csum[c], s);
    atomicAdd(&csq[c], sq);
}

__global__ void k_bnapply_split(const float* __restrict__ in, float* __restrict__ out,
                                __nv_bfloat16* __restrict__ hi, __nv_bfloat16* __restrict__ lo,
                                const float* __restrict__ csum, const float* __restrict__ csq,
                                const float* __restrict__ gamma, const float* __restrict__ beta,
                                int N, int F, int store_f32, int store_bf16) {
    int idx = blockIdx.x * blockDim.x + threadIdx.x;
    if (idx >= N * F) return;
    int c = idx % F;
    float invN = 1.f / (float)N;
    float mean = csum[c] * invN;
    float var = csq[c] * invN - mean * mean;
    float v = (in[idx] - mean) * rsqrtf(var + 1e-5f) * gamma[c] + beta[c];
    v = v > 0.f ? v : (__expf(v) - 1.f);
    if (store_f32) out[idx] = v;
    if (store_bf16) {
        __nv_bfloat16 h = __float2bfloat16(v);
        hi[idx] = h;
        lo[idx] = __float2bfloat16(v - __bfloat162float(h));
    }
}

// ---------------------------------------------------------------------------
// Host orchestration
// ---------------------------------------------------------------------------
extern "C" void kernel_launch(void* const* d_in, const int* in_sizes, int n_in,
                              void* d_out, int out_size) {
    const float* x = (const float*)d_in[0];
    const int* ei = (const int*)d_in[1];
    int N = in_sizes[0] / 512;
    int E = in_sizes[1] / 2;
    int Etot = E + N;

    float *p_h, *p_y, *p_agg, *p_as, *p_ad, *p_w, *p_invs, *p_csum, *p_csq;
    int *p_deg, *p_rowptr, *p_cursor, *p_srcs, *p_bsums;
    __nv_bfloat16 *p_ahi, *p_alo, *p_bhi, *p_blo;
    cudaGetSymbolAddress((void**)&p_h, g_h);
    cudaGetSymbolAddress((void**)&p_y, g_y);
    cudaGetSymbolAddress((void**)&p_agg, g_agg);
    cudaGetSymbolAddress((void**)&p_as, g_as);
    cudaGetSymbolAddress((void**)&p_ad, g_ad);
    cudaGetSymbolAddress((void**)&p_w, g_w);
    cudaGetSymbolAddress((void**)&p_invs, g_invs);
    cudaGetSymbolAddress((void**)&p_csum, g_colsum);
    cudaGetSymbolAddress((void**)&p_csq, g_colsq);
    cudaGetSymbolAddress((void**)&p_deg, g_deg);
    cudaGetSymbolAddress((void**)&p_rowptr, g_rowptr);
    cudaGetSymbolAddress((void**)&p_cursor, g_cursor);
    cudaGetSymbolAddress((void**)&p_srcs, g_srcs);
    cudaGetSymbolAddress((void**)&p_bsums, g_bsums);
    cudaGetSymbolAddress((void**)&p_ahi, g_ahi);
    cudaGetSymbolAddress((void**)&p_alo, g_alo);
    cudaGetSymbolAddress((void**)&p_bhi, g_bhi);
    cudaGetSymbolAddress((void**)&p_blo, g_blo);

    cudaFuncSetAttribute(k_mma_gemm, cudaFuncAttributeMaxDynamicSharedMemorySize, MMA_SMEM);

    struct Cfg { int Fin, H, C, iW; bool bn; };
    const Cfg cfgs[4] = {
        {512, 8, 64, 2, true},
        {512, 4, 64, 8, true},
        {256, 2, 64, 14, true},
        {128, 1, 16, 20, false},
    };

    // ---- Layer-1 prep + GEMM ----
    {
        int nel = N * 512;
        k_zero_int<<<(N + 255) / 256, 256>>>(p_deg, N);
        k_split<<<(nel / 4 + 255) / 256, 256>>>(x, p_ahi, p_alo, nel);
        int nw = 512 * 512;
        k_split<<<(nw / 4 + 255) / 256, 256>>>((const float*)d_in[2], p_bhi, p_blo, nw);
        dim3 gg(512 / 128, (N + 127) / 128);
        k_mma_gemm<<<gg, 256, MMA_SMEM>>>(p_ahi, p_alo, p_bhi, p_blo, p_h, N, 512, 512,
                                          (const float*)d_in[3], (const float*)d_in[4],
                                          p_as, p_ad, 8);
    }

    // ---- CSR build ----
    k_hist<<<(Etot + 255) / 256, 256>>>(ei, E, N, p_deg);
    int nblk = (N + SCAN_B - 1) / SCAN_B;
    k_scan1<<<nblk, SCAN_B>>>(p_deg, p_rowptr, p_bsums, N);
    k_scan2<<<1, 32>>>(p_bsums, nblk);
    k_scan3<<<(N + 255) / 256, 256>>>(p_rowptr, p_bsums, N, Etot, p_cursor);
    k_scatter<<<(Etot + 255) / 256, 256>>>(ei, E, N, p_cursor, p_srcs);

    const float* in = x;
    int nwarpblk = (N + 7) / 8;
    for (int li = 0; li < 4; li++) {
        const Cfg& cf = cfgs[li];
        int F = cf.H * cf.C;
        const float* W  = (const float*)d_in[cf.iW + 0];
        const float* as = (const float*)d_in[cf.iW + 1];
        const float* ad = (const float*)d_in[cf.iW + 2];
        const float* bi = (const float*)d_in[cf.iW + 3];

        if (li >= 1 && li < 3) {
            int nw = cf.Fin * F;
            k_split<<<(nw / 4 + 255) / 256, 256>>>(W, p_bhi, p_blo, nw);
            dim3 gg(F / 128, (N + 127) / 128);
            k_mma_gemm<<<gg, 256, MMA_SMEM>>>(p_ahi, p_alo, p_bhi, p_blo, p_h, N, cf.Fin, F,
                                              as, ad, p_as, p_ad, cf.H);
        } else if (li == 3) {
            dim3 ggrid((F + 63) / 64, (N + 63) / 64);
            k_sgemm<<<ggrid, 256>>>(in, W, p_h, N, cf.Fin, F);
            int pairs = N * cf.H;
            k_attcoef<<<(pairs + 3) / 4, 128>>>(p_h, as, ad, p_as, p_ad, N, cf.H, cf.C);
            // fused softmax + aggregation + bias + log_softmax
            k_l4_tail<<<nwarpblk, 256>>>(p_h, p_as, p_ad, p_rowptr, p_srcs, bi,
                                         (float*)d_out, N);
            break;
        }

        switch (cf.H) {
            case 8: k_attn<8><<<nwarpblk, 256>>>(p_as, p_ad, p_rowptr, p_srcs, p_w, p_invs, N, Etot); break;
            case 4: k_attn<4><<<nwarpblk, 256>>>(p_as, p_ad, p_rowptr, p_srcs, p_w, p_invs, N, Etot); break;
            default: k_attn<2><<<nwarpblk, 256>>>(p_as, p_ad, p_rowptr, p_srcs, p_w, p_invs, N, Etot); break;
        }

        int T = (F >= 128) ? (F >> 2) : 32;
        k_agg<<<N, T>>>(p_h, p_w, p_invs, p_rowptr, p_srcs, bi, p_agg, cf.H, cf.C, F, Etot);

        const float* gamma = (const float*)d_in[cf.iW + 4];
        const float* beta  = (const float*)d_in[cf.iW + 5];
        k_zero_f2<<<1, F>>>(p_csum, p_csq, F);
        k_bnstats<<<240, F>>>(p_agg, p_csum, p_csq, N, F);
        int store_f32 = (li == 2) ? 1 : 0;
        int store_bf16 = (li < 2) ? 1 : 0;
        k_bnapply_split<<<(N * F + 255) / 256, 256>>>(p_agg, p_y, p_ahi, p_alo,
                                                      p_csum, p_csq, gamma, beta, N, F,
                                                      store_f32, store_bf16);
        in = p_y;
    }
}